// round 7
// baseline (speedup 1.0000x reference)
#include <cuda_runtime.h>
#include <cuda_bf16.h>
#include <cstdint>

#define B_ 64
#define N_ 32
#define H_ 24
#define F_ 256

// ---------------- scratch ----------------
__device__ float g_QWq[(size_t)B_ * N_ * F_];              // [b][n][g]
__device__ float g_logits[(size_t)B_ * N_ * H_];           // [b][n][h]
__device__ float g_VWv[(size_t)B_ * N_ * H_ * F_];         // [b][n][h][g]

// ---------------- helpers ----------------
__device__ __forceinline__ uint32_t s2u(const void* p) {
    return (uint32_t)__cvta_generic_to_shared(p);
}
__device__ __forceinline__ uint32_t bpack(float a, float b, float& ra, float& rb) {
    __nv_bfloat16 ha = __float2bfloat16(a), hb = __float2bfloat16(b);
    ra = a - __bfloat162float(ha);
    rb = b - __bfloat162float(hb);
    return (uint32_t)__bfloat16_as_ushort(ha) | ((uint32_t)__bfloat16_as_ushort(hb) << 16);
}
__device__ __forceinline__ uint32_t bpack1(float a, float b) {
    __nv_bfloat16 ha = __float2bfloat16(a), hb = __float2bfloat16(b);
    return (uint32_t)__bfloat16_as_ushort(ha) | ((uint32_t)__bfloat16_as_ushort(hb) << 16);
}
__device__ __forceinline__ uint2 lds64(uint32_t a) {
    uint2 r;
    asm volatile("ld.shared.v2.u32 {%0,%1}, [%2];" : "=r"(r.x), "=r"(r.y) : "r"(a));
    return r;
}
__device__ __forceinline__ void mma4(float* c, uint2 rA, uint2 rA8, uint2 b) {
    asm volatile("mma.sync.aligned.m16n8k16.row.col.f32.bf16.bf16.f32 "
                 "{%0,%1,%2,%3}, {%4,%5,%6,%7}, {%8,%9}, {%0,%1,%2,%3};"
                 : "+f"(c[0]), "+f"(c[1]), "+f"(c[2]), "+f"(c[3])
                 : "r"(rA.x), "r"(rA8.x), "r"(rA.y), "r"(rA8.y), "r"(b.x), "r"(b.y));
}

// converted-tile buffers (double-buffered)
#define OFF_WH 0        // 8192: W hi [256 g][32B interleaved]
#define OFF_WL 8192     // 8192: W lo
#define OFF_AH 16384    // 2048: A hi [64 r][32B]
#define OFF_AL 18432    // 2048
#define BUFSZ  20480
#define SMEM_SZ (2 * BUFSZ)   // 40960

// Core: C[64 b][256 g] = A[64x256] @ W[256x256]; P passes.
// LOGITS: pass0 -> logits (dot with g_QWq + bk); last pass (or P==1) -> gmem write (+bw).
template <int P, bool LOGITS>
__device__ __forceinline__ void proj_core(
    char* smk, uint32_t sb,
    const float* __restrict__ A0, const float* __restrict__ A1, long sA,
    const float* __restrict__ W0, const float* __restrict__ W1,
    const float* __restrict__ bkp,   // logits bias (pass0, LOGITS only)
    const float* __restrict__ bwp,   // write bias
    float* __restrict__ ob, long pitch,
    int n, int h, float (*sred)[64])
{
    const int t = threadIdx.x;
    const int w = t >> 5, l = t & 31;
    const int mhalf = w >> 2, wq = w & 3;
    const int c = l & 3;
    const int rho = l >> 2;
    const uint32_t x = ((l >> 4) & 1) << 2;
    const uint32_t woff = (uint32_t)(((2 * c) ^ x) << 2);

    float acc[2][8][4];
    #pragma unroll
    for (int i = 0; i < 2; i++)
        #pragma unroll
        for (int j = 0; j < 8; j++)
            #pragma unroll
            for (int k = 0; k < 4; k++) acc[i][j][k] = 0.f;

    float wv[16];
    float4 av;
    const int ar = t >> 2, aq = t & 3;

    // stage chunk gc: W column t (16 f-rows) + A quarter-row, straight to registers
    auto loadc = [&](int gc) {
        const int pass = gc >> 4, cc = gc & 15;
        const float* Wp = ((P == 1 || pass == 0) ? W0 : W1) + (size_t)cc * 16 * F_ + t;
        #pragma unroll
        for (int f = 0; f < 16; ++f) wv[f] = Wp[(size_t)f * F_];
        const float* Ap = ((P == 1 || pass == 0) ? A0 : A1) + (long)ar * sA + cc * 16 + aq * 4;
        av = *(const float4*)Ap;
    };

    loadc(0);

    #pragma unroll 1
    for (int gc = 0; gc < 16 * P; ++gc) {
        const int buf = gc & 1;
        const uint32_t bufb = sb + (uint32_t)buf * BUFSZ;
        char* bufp = smk + buf * BUFSZ;

        // ---- convert W from regs -> WH/WL (interleaved layout, conflict-free) ----
        {
            uint32_t hi[8], lo[8];
            #pragma unroll
            for (int j = 0; j < 8; ++j) {
                float ra, rb;
                hi[j] = bpack(wv[2 * j], wv[2 * j + 1], ra, rb);
                lo[j] = bpack1(ra, rb);
            }
            const int s0 = ((t >> 2) & 1) << 4;
            char* bh = bufp + OFF_WH + t * 32;
            char* bl = bufp + OFF_WL + t * 32;
            *(uint4*)(bh + s0)        = make_uint4(hi[0], hi[4], hi[1], hi[5]);
            *(uint4*)(bh + (16 ^ s0)) = make_uint4(hi[2], hi[6], hi[3], hi[7]);
            *(uint4*)(bl + s0)        = make_uint4(lo[0], lo[4], lo[1], lo[5]);
            *(uint4*)(bl + (16 ^ s0)) = make_uint4(lo[2], lo[6], lo[3], lo[7]);
        }
        // ---- convert A from regs -> AH/AL ----
        {
            float r0, r1, r2, r3;
            uint32_t h0 = bpack(av.x, av.y, r0, r1);
            uint32_t h1 = bpack(av.z, av.w, r2, r3);
            uint32_t l0 = bpack1(r0, r1);
            uint32_t l1 = bpack1(r2, r3);
            const int iw0 = (aq < 2) ? 4 * aq : 4 * aq - 7;
            const int iw1 = (aq < 2) ? 4 * aq + 2 : 4 * aq - 5;
            const int x4 = ((ar >> 2) & 1) << 2;
            char* ah = bufp + OFF_AH + ar * 32;
            char* al = bufp + OFF_AL + ar * 32;
            *(uint32_t*)(ah + ((iw0 ^ x4) << 2)) = h0;
            *(uint32_t*)(ah + ((iw1 ^ x4) << 2)) = h1;
            *(uint32_t*)(al + ((iw0 ^ x4) << 2)) = l0;
            *(uint32_t*)(al + ((iw1 ^ x4) << 2)) = l1;
        }

        if (gc + 1 < 16 * P) loadc(gc + 1);   // prefetch next chunk into regs
        __syncthreads();

        // ---- A fragments hoisted to registers (once per chunk) ----
        uint2 fa[2][4];
        #pragma unroll
        for (int mt = 0; mt < 2; ++mt) {
            const int r1 = mhalf * 32 + mt * 16 + rho;
            fa[mt][0] = lds64(bufb + OFF_AH + r1 * 32 + woff);
            fa[mt][1] = lds64(bufb + OFF_AH + (r1 + 8) * 32 + woff);
            fa[mt][2] = lds64(bufb + OFF_AL + r1 * 32 + woff);
            fa[mt][3] = lds64(bufb + OFF_AL + (r1 + 8) * 32 + woff);
        }
        // ---- nt-outer: each W fragment loaded once, used by both m-tiles ----
        #pragma unroll
        for (int nt = 0; nt < 8; ++nt) {
            const int g = wq * 64 + nt * 8 + rho;
            uint2 bh = lds64(bufb + OFF_WH + g * 32 + woff);
            uint2 bl = lds64(bufb + OFF_WL + g * 32 + woff);
            #pragma unroll
            for (int mt = 0; mt < 2; ++mt) {
                mma4(acc[mt][nt], fa[mt][0], fa[mt][1], bh);
                mma4(acc[mt][nt], fa[mt][0], fa[mt][1], bl);
                mma4(acc[mt][nt], fa[mt][2], fa[mt][3], bh);
            }
        }

        // ---- end-of-pass epilogues ----
        if ((gc & 15) == 15) {
            const int pass = gc >> 4;
            if (LOGITS && pass == 0) {
                // logits[b] = sum_g (C[b][g] + bk[g]) * QWq[b][n][g]
                float p[4] = {0.f, 0.f, 0.f, 0.f};
                #pragma unroll
                for (int nt = 0; nt < 8; ++nt) {
                    const int g0 = wq * 64 + nt * 8 + 2 * c;
                    const float2 bkv = *(const float2*)(bkp + g0);
                    #pragma unroll
                    for (int rr = 0; rr < 4; ++rr) {
                        const int row = mhalf * 32 + (rr >> 1) * 16 + (rr & 1) * 8 + rho;
                        const float2 qv = *(const float2*)(g_QWq + ((size_t)row * N_ + n) * F_ + g0);
                        p[rr] += (acc[rr >> 1][nt][(rr & 1) * 2]     + bkv.x) * qv.x
                               + (acc[rr >> 1][nt][(rr & 1) * 2 + 1] + bkv.y) * qv.y;
                    }
                }
                #pragma unroll
                for (int rr = 0; rr < 4; ++rr) {
                    p[rr] += __shfl_xor_sync(0xffffffffu, p[rr], 1);
                    p[rr] += __shfl_xor_sync(0xffffffffu, p[rr], 2);
                }
                if (c == 0) {
                    #pragma unroll
                    for (int rr = 0; rr < 4; ++rr)
                        sred[wq][mhalf * 32 + (rr >> 1) * 16 + (rr & 1) * 8 + rho] = p[rr];
                }
                __syncthreads();
                if (t < 64) {
                    float s = sred[0][t] + sred[1][t] + sred[2][t] + sred[3][t];
                    g_logits[((size_t)t * N_ + n) * H_ + h] = s;
                }
                #pragma unroll
                for (int i = 0; i < 2; i++)
                    #pragma unroll
                    for (int j = 0; j < 8; j++)
                        #pragma unroll
                        for (int k = 0; k < 4; k++) acc[i][j][k] = 0.f;
            } else {
                // gmem write (+ bias)
                #pragma unroll
                for (int nt = 0; nt < 8; ++nt) {
                    const int g0 = wq * 64 + nt * 8 + 2 * c;
                    const float2 bv2 = *(const float2*)(bwp + g0);
                    #pragma unroll
                    for (int mt = 0; mt < 2; ++mt) {
                        const int r1 = mhalf * 32 + mt * 16 + rho;
                        float2 v0, v1;
                        v0.x = acc[mt][nt][0] + bv2.x; v0.y = acc[mt][nt][1] + bv2.y;
                        v1.x = acc[mt][nt][2] + bv2.x; v1.y = acc[mt][nt][3] + bv2.y;
                        *(float2*)(ob + (long)r1 * pitch + g0) = v0;
                        *(float2*)(ob + (long)(r1 + 8) * pitch + g0) = v1;
                    }
                }
            }
        }
    }
}

// ---------------- kernels ----------------
__global__ void __launch_bounds__(256, 2) k_kv(const float* __restrict__ Kt,
                                               const float* __restrict__ Vt,
                                               const float* __restrict__ Wk,
                                               const float* __restrict__ bk,
                                               const float* __restrict__ Wv,
                                               const float* __restrict__ bv)
{
    extern __shared__ char smk[];
    __shared__ float sred[4][64];
    const int h = blockIdx.x, n = blockIdx.y;
    const size_t nh = (size_t)n * H_ + h;
    proj_core<2, true>(smk, s2u(smk),
                       Kt + ((size_t)h * N_ + n) * F_, Vt + ((size_t)h * N_ + n) * F_,
                       (long)H_ * N_ * F_,
                       Wk + nh * F_ * F_, Wv + nh * F_ * F_,
                       bk + nh * F_, bv + nh * F_,
                       g_VWv + nh * F_, (long)N_ * H_ * F_, n, h, sred);
}

__global__ void __launch_bounds__(256, 2) k_qwq(const float* __restrict__ Q,
                                                const float* __restrict__ Wq,
                                                const float* __restrict__ bq)
{
    extern __shared__ char smk[];
    __shared__ float sred[4][64];
    const int n = blockIdx.x;
    proj_core<1, false>(smk, s2u(smk),
                        Q + (size_t)n * F_, Q + (size_t)n * F_, (long)N_ * F_,
                        Wq + (size_t)n * F_ * F_, Wq + (size_t)n * F_ * F_,
                        bq + (size_t)n * F_, bq + (size_t)n * F_,
                        g_QWq + (size_t)n * F_, (long)N_ * F_, n, 0, sred);
}

// softmax over H; writes scores to out tail region
__global__ void k_softmax(float* __restrict__ out)
{
    const int idx = blockIdx.x * 256 + threadIdx.x;   // b*N+n
    const float* lp = g_logits + (size_t)idx * H_;
    float v[H_];
    float m = -3.4e38f;
    #pragma unroll
    for (int h = 0; h < H_; ++h) { v[h] = lp[h]; m = fmaxf(m, v[h]); }
    float s = 0.f;
    #pragma unroll
    for (int h = 0; h < H_; ++h) { v[h] = expf(v[h] - m); s += v[h]; }
    const float inv = 1.0f / s;
    float* sp = out + (size_t)B_ * N_ * F_ + (size_t)idx * H_;
    #pragma unroll
    for (int h = 0; h < H_; ++h) sp[h] = v[h] * inv;
}

// heads[b][n][g] = sum_h scores[b][n][h] * VWv[b][n][h][g]; 4 bn per CTA, float4
__global__ void __launch_bounds__(256) k_heads(float* __restrict__ out)
{
    __shared__ float s[4][H_];
    const int bn0 = blockIdx.x * 4;
    const int t = threadIdx.x;
    if (t < 4 * H_) {
        const int bl = t / H_, hh = t % H_;
        s[bl][hh] = out[(size_t)B_ * N_ * F_ + (size_t)(bn0 + bl) * H_ + hh];
    }
    __syncthreads();
    const int bl = t >> 6;
    const int gq = (t & 63) * 4;
    const float* vp = g_VWv + (size_t)(bn0 + bl) * H_ * F_ + gq;
    float4 a = make_float4(0.f, 0.f, 0.f, 0.f);
    #pragma unroll
    for (int h = 0; h < H_; ++h) {
        const float4 v = *(const float4*)(vp + (size_t)h * F_);
        const float sc = s[bl][h];
        a.x += sc * v.x; a.y += sc * v.y; a.z += sc * v.z; a.w += sc * v.w;
    }
    *(float4*)(out + (size_t)(bn0 + bl) * F_ + gq) = a;
}

// ---------------- launch ----------------
extern "C" void kernel_launch(void* const* d_in, const int* in_sizes, int n_in,
                              void* d_out, int out_size)
{
    (void)in_sizes; (void)n_in; (void)out_size;
    const float* Q  = (const float*)d_in[0];
    const float* K  = (const float*)d_in[1];
    const float* V  = (const float*)d_in[2];
    const float* Wq = (const float*)d_in[3];
    const float* bq = (const float*)d_in[4];
    const float* Wk = (const float*)d_in[5];
    const float* bk = (const float*)d_in[6];
    const float* Wv = (const float*)d_in[7];
    const float* bv = (const float*)d_in[8];
    float* out = (float*)d_out;

    k_qwq<<<N_, 256, SMEM_SZ>>>(Q, Wq, bq);
    k_kv<<<dim3(H_, N_), 256, SMEM_SZ>>>(K, V, Wk, bk, Wv, bv);
    k_softmax<<<(B_ * N_) / 256, 256>>>(out);
    k_heads<<<(B_ * N_) / 4, 256>>>(out);
}

// round 8
// speedup vs baseline: 1.0043x; 1.0043x over previous
#include <cuda_runtime.h>
#include <cuda_bf16.h>
#include <cstdint>

#define B_ 64
#define N_ 32
#define H_ 24
#define F_ 256

// ---------------- scratch ----------------
__device__ float g_QWq[(size_t)B_ * N_ * F_];              // [b][n][g]
__device__ float g_logits[(size_t)B_ * N_ * H_];           // [b][n][h]
__device__ float g_VWv[(size_t)B_ * N_ * H_ * F_];         // [b][n][h][g]

// ---------------- helpers ----------------
__device__ __forceinline__ uint32_t s2u(const void* p) {
    return (uint32_t)__cvta_generic_to_shared(p);
}
__device__ __forceinline__ uint32_t bpack(float a, float b, float& ra, float& rb) {
    __nv_bfloat16 ha = __float2bfloat16(a), hb = __float2bfloat16(b);
    ra = a - __bfloat162float(ha);
    rb = b - __bfloat162float(hb);
    return (uint32_t)__bfloat16_as_ushort(ha) | ((uint32_t)__bfloat16_as_ushort(hb) << 16);
}
__device__ __forceinline__ uint32_t bpack1(float a, float b) {
    __nv_bfloat16 ha = __float2bfloat16(a), hb = __float2bfloat16(b);
    return (uint32_t)__bfloat16_as_ushort(ha) | ((uint32_t)__bfloat16_as_ushort(hb) << 16);
}
__device__ __forceinline__ uint2 lds64(uint32_t a) {
    uint2 r;
    asm volatile("ld.shared.v2.u32 {%0,%1}, [%2];" : "=r"(r.x), "=r"(r.y) : "r"(a));
    return r;
}
__device__ __forceinline__ void mma4(float* c, uint2 rA, uint2 rA8, uint2 b) {
    asm volatile("mma.sync.aligned.m16n8k16.row.col.f32.bf16.bf16.f32 "
                 "{%0,%1,%2,%3}, {%4,%5,%6,%7}, {%8,%9}, {%0,%1,%2,%3};"
                 : "+f"(c[0]), "+f"(c[1]), "+f"(c[2]), "+f"(c[3])
                 : "r"(rA.x), "r"(rA8.x), "r"(rA.y), "r"(rA8.y), "r"(b.x), "r"(b.y));
}

// converted-tile buffers (double-buffered)
#define OFF_WH 0        // 8192: W hi [256 g][32B interleaved]
#define OFF_WL 8192     // 8192: W lo
#define OFF_AH 16384    // 2048: A hi [64 r][32B]
#define OFF_AL 18432    // 2048
#define BUFSZ  20480
#define SMEM_SZ (2 * BUFSZ)   // 40960

// Core: C[64 b][256 g] = A[64x256] @ W[256x256]; P passes.
// LOGITS: pass0 -> logits (dot with g_QWq + bk); last pass (or P==1) -> gmem write (+bw).
template <int P, bool LOGITS>
__device__ __forceinline__ void proj_core(
    char* smk, uint32_t sb,
    const float* __restrict__ A0, const float* __restrict__ A1, long sA,
    const float* __restrict__ W0, const float* __restrict__ W1,
    const float* __restrict__ bkp,   // logits bias (pass0, LOGITS only)
    const float* __restrict__ bwp,   // write bias
    float* __restrict__ ob, long pitch,
    int n, int h, float (*sred)[64])
{
    const int t = threadIdx.x;
    const int w = t >> 5, l = t & 31;
    const int mhalf = w >> 2, wq = w & 3;
    const int c = l & 3;
    const int rho = l >> 2;
    const uint32_t x = ((l >> 4) & 1) << 2;
    const uint32_t woff = (uint32_t)(((2 * c) ^ x) << 2);

    float acc[2][8][4];
    #pragma unroll
    for (int i = 0; i < 2; i++)
        #pragma unroll
        for (int j = 0; j < 8; j++)
            #pragma unroll
            for (int k = 0; k < 4; k++) acc[i][j][k] = 0.f;

    float wv[16];
    float4 av;
    const int ar = t >> 2, aq = t & 3;

    // stage chunk gc: W column t (16 f-rows) + A quarter-row, straight to registers
    auto loadc = [&](int gc) {
        const int pass = gc >> 4, cc = gc & 15;
        const float* Wp = ((P == 1 || pass == 0) ? W0 : W1) + (size_t)cc * 16 * F_ + t;
        #pragma unroll
        for (int f = 0; f < 16; ++f) wv[f] = Wp[(size_t)f * F_];
        const float* Ap = ((P == 1 || pass == 0) ? A0 : A1) + (long)ar * sA + cc * 16 + aq * 4;
        av = *(const float4*)Ap;
    };

    loadc(0);

    #pragma unroll 1
    for (int gc = 0; gc < 16 * P; ++gc) {
        const int buf = gc & 1;
        const uint32_t bufb = sb + (uint32_t)buf * BUFSZ;
        char* bufp = smk + buf * BUFSZ;

        // ---- convert W from regs -> WH/WL (interleaved layout, conflict-free) ----
        {
            uint32_t hi[8], lo[8];
            #pragma unroll
            for (int j = 0; j < 8; ++j) {
                float ra, rb;
                hi[j] = bpack(wv[2 * j], wv[2 * j + 1], ra, rb);
                lo[j] = bpack1(ra, rb);
            }
            const int s0 = ((t >> 2) & 1) << 4;
            char* bh = bufp + OFF_WH + t * 32;
            char* bl = bufp + OFF_WL + t * 32;
            *(uint4*)(bh + s0)        = make_uint4(hi[0], hi[4], hi[1], hi[5]);
            *(uint4*)(bh + (16 ^ s0)) = make_uint4(hi[2], hi[6], hi[3], hi[7]);
            *(uint4*)(bl + s0)        = make_uint4(lo[0], lo[4], lo[1], lo[5]);
            *(uint4*)(bl + (16 ^ s0)) = make_uint4(lo[2], lo[6], lo[3], lo[7]);
        }
        // ---- convert A from regs -> AH/AL ----
        {
            float r0, r1, r2, r3;
            uint32_t h0 = bpack(av.x, av.y, r0, r1);
            uint32_t h1 = bpack(av.z, av.w, r2, r3);
            uint32_t l0 = bpack1(r0, r1);
            uint32_t l1 = bpack1(r2, r3);
            const int iw0 = (aq < 2) ? 4 * aq : 4 * aq - 7;
            const int iw1 = (aq < 2) ? 4 * aq + 2 : 4 * aq - 5;
            const int x4 = ((ar >> 2) & 1) << 2;
            char* ah = bufp + OFF_AH + ar * 32;
            char* al = bufp + OFF_AL + ar * 32;
            *(uint32_t*)(ah + ((iw0 ^ x4) << 2)) = h0;
            *(uint32_t*)(ah + ((iw1 ^ x4) << 2)) = h1;
            *(uint32_t*)(al + ((iw0 ^ x4) << 2)) = l0;
            *(uint32_t*)(al + ((iw1 ^ x4) << 2)) = l1;
        }

        if (gc + 1 < 16 * P) loadc(gc + 1);   // prefetch next chunk into regs
        __syncthreads();

        // ---- A fragments hoisted to registers (once per chunk) ----
        uint2 fa[2][4];
        #pragma unroll
        for (int mt = 0; mt < 2; ++mt) {
            const int r1 = mhalf * 32 + mt * 16 + rho;
            fa[mt][0] = lds64(bufb + OFF_AH + r1 * 32 + woff);
            fa[mt][1] = lds64(bufb + OFF_AH + (r1 + 8) * 32 + woff);
            fa[mt][2] = lds64(bufb + OFF_AL + r1 * 32 + woff);
            fa[mt][3] = lds64(bufb + OFF_AL + (r1 + 8) * 32 + woff);
        }
        // ---- nt-outer: each W fragment loaded once, used by both m-tiles ----
        #pragma unroll
        for (int nt = 0; nt < 8; ++nt) {
            const int g = wq * 64 + nt * 8 + rho;
            uint2 bh = lds64(bufb + OFF_WH + g * 32 + woff);
            uint2 bl = lds64(bufb + OFF_WL + g * 32 + woff);
            #pragma unroll
            for (int mt = 0; mt < 2; ++mt) {
                mma4(acc[mt][nt], fa[mt][0], fa[mt][1], bh);
                mma4(acc[mt][nt], fa[mt][0], fa[mt][1], bl);
                mma4(acc[mt][nt], fa[mt][2], fa[mt][3], bh);
            }
        }

        // ---- end-of-pass epilogues ----
        if ((gc & 15) == 15) {
            const int pass = gc >> 4;
            if (LOGITS && pass == 0) {
                // logits[b] = sum_g (C[b][g] + bk[g]) * QWq[b][n][g]
                float p[4] = {0.f, 0.f, 0.f, 0.f};
                #pragma unroll
                for (int nt = 0; nt < 8; ++nt) {
                    const int g0 = wq * 64 + nt * 8 + 2 * c;
                    const float2 bkv = *(const float2*)(bkp + g0);
                    #pragma unroll
                    for (int rr = 0; rr < 4; ++rr) {
                        const int row = mhalf * 32 + (rr >> 1) * 16 + (rr & 1) * 8 + rho;
                        const float2 qv = *(const float2*)(g_QWq + ((size_t)row * N_ + n) * F_ + g0);
                        p[rr] += (acc[rr >> 1][nt][(rr & 1) * 2]     + bkv.x) * qv.x
                               + (acc[rr >> 1][nt][(rr & 1) * 2 + 1] + bkv.y) * qv.y;
                    }
                }
                #pragma unroll
                for (int rr = 0; rr < 4; ++rr) {
                    p[rr] += __shfl_xor_sync(0xffffffffu, p[rr], 1);
                    p[rr] += __shfl_xor_sync(0xffffffffu, p[rr], 2);
                }
                if (c == 0) {
                    #pragma unroll
                    for (int rr = 0; rr < 4; ++rr)
                        sred[wq][mhalf * 32 + (rr >> 1) * 16 + (rr & 1) * 8 + rho] = p[rr];
                }
                __syncthreads();
                if (t < 64) {
                    float s = sred[0][t] + sred[1][t] + sred[2][t] + sred[3][t];
                    g_logits[((size_t)t * N_ + n) * H_ + h] = s;
                }
                #pragma unroll
                for (int i = 0; i < 2; i++)
                    #pragma unroll
                    for (int j = 0; j < 8; j++)
                        #pragma unroll
                        for (int k = 0; k < 4; k++) acc[i][j][k] = 0.f;
            } else {
                // gmem write (+ bias)
                #pragma unroll
                for (int nt = 0; nt < 8; ++nt) {
                    const int g0 = wq * 64 + nt * 8 + 2 * c;
                    const float2 bv2 = *(const float2*)(bwp + g0);
                    #pragma unroll
                    for (int mt = 0; mt < 2; ++mt) {
                        const int r1 = mhalf * 32 + mt * 16 + rho;
                        float2 v0, v1;
                        v0.x = acc[mt][nt][0] + bv2.x; v0.y = acc[mt][nt][1] + bv2.y;
                        v1.x = acc[mt][nt][2] + bv2.x; v1.y = acc[mt][nt][3] + bv2.y;
                        *(float2*)(ob + (long)r1 * pitch + g0) = v0;
                        *(float2*)(ob + (long)(r1 + 8) * pitch + g0) = v1;
                    }
                }
            }
        }
    }
}

// ---------------- kernels ----------------
__global__ void __launch_bounds__(256, 2) k_kv(const float* __restrict__ Kt,
                                               const float* __restrict__ Vt,
                                               const float* __restrict__ Wk,
                                               const float* __restrict__ bk,
                                               const float* __restrict__ Wv,
                                               const float* __restrict__ bv)
{
    extern __shared__ char smk[];
    __shared__ float sred[4][64];
    const int h = blockIdx.x, n = blockIdx.y;
    const size_t nh = (size_t)n * H_ + h;
    proj_core<2, true>(smk, s2u(smk),
                       Kt + ((size_t)h * N_ + n) * F_, Vt + ((size_t)h * N_ + n) * F_,
                       (long)H_ * N_ * F_,
                       Wk + nh * F_ * F_, Wv + nh * F_ * F_,
                       bk + nh * F_, bv + nh * F_,
                       g_VWv + nh * F_, (long)N_ * H_ * F_, n, h, sred);
}

__global__ void __launch_bounds__(256, 2) k_qwq(const float* __restrict__ Q,
                                                const float* __restrict__ Wq,
                                                const float* __restrict__ bq)
{
    extern __shared__ char smk[];
    __shared__ float sred[4][64];
    const int n = blockIdx.x;
    proj_core<1, false>(smk, s2u(smk),
                        Q + (size_t)n * F_, Q + (size_t)n * F_, (long)N_ * F_,
                        Wq + (size_t)n * F_ * F_, Wq + (size_t)n * F_ * F_,
                        bq + (size_t)n * F_, bq + (size_t)n * F_,
                        g_QWq + (size_t)n * F_, (long)N_ * F_, n, 0, sred);
}

// softmax over H; writes scores to out tail region
__global__ void k_softmax(float* __restrict__ out)
{
    const int idx = blockIdx.x * 256 + threadIdx.x;   // b*N+n
    const float* lp = g_logits + (size_t)idx * H_;
    float v[H_];
    float m = -3.4e38f;
    #pragma unroll
    for (int h = 0; h < H_; ++h) { v[h] = lp[h]; m = fmaxf(m, v[h]); }
    float s = 0.f;
    #pragma unroll
    for (int h = 0; h < H_; ++h) { v[h] = expf(v[h] - m); s += v[h]; }
    const float inv = 1.0f / s;
    float* sp = out + (size_t)B_ * N_ * F_ + (size_t)idx * H_;
    #pragma unroll
    for (int h = 0; h < H_; ++h) sp[h] = v[h] * inv;
}

// heads[b][n][g] = sum_h scores[b][n][h] * VWv[b][n][h][g]; 4 bn per CTA, float4
__global__ void __launch_bounds__(256) k_heads(float* __restrict__ out)
{
    __shared__ float s[4][H_];
    const int bn0 = blockIdx.x * 4;
    const int t = threadIdx.x;
    if (t < 4 * H_) {
        const int bl = t / H_, hh = t % H_;
        s[bl][hh] = out[(size_t)B_ * N_ * F_ + (size_t)(bn0 + bl) * H_ + hh];
    }
    __syncthreads();
    const int bl = t >> 6;
    const int gq = (t & 63) * 4;
    const float* vp = g_VWv + (size_t)(bn0 + bl) * H_ * F_ + gq;
    float4 a = make_float4(0.f, 0.f, 0.f, 0.f);
    #pragma unroll
    for (int h = 0; h < H_; ++h) {
        const float4 v = *(const float4*)(vp + (size_t)h * F_);
        const float sc = s[bl][h];
        a.x += sc * v.x; a.y += sc * v.y; a.z += sc * v.z; a.w += sc * v.w;
    }
    *(float4*)(out + (size_t)(bn0 + bl) * F_ + gq) = a;
}

// ---------------- launch ----------------
extern "C" void kernel_launch(void* const* d_in, const int* in_sizes, int n_in,
                              void* d_out, int out_size)
{
    (void)in_sizes; (void)n_in; (void)out_size;
    const float* Q  = (const float*)d_in[0];
    const float* K  = (const float*)d_in[1];
    const float* V  = (const float*)d_in[2];
    const float* Wq = (const float*)d_in[3];
    const float* bq = (const float*)d_in[4];
    const float* Wk = (const float*)d_in[5];
    const float* bk = (const float*)d_in[6];
    const float* Wv = (const float*)d_in[7];
    const float* bv = (const float*)d_in[8];
    float* out = (float*)d_out;

    k_qwq<<<N_, 256, SMEM_SZ>>>(Q, Wq, bq);
    k_kv<<<dim3(H_, N_), 256, SMEM_SZ>>>(K, V, Wk, bk, Wv, bv);
    k_softmax<<<(B_ * N_) / 256, 256>>>(out);
    k_heads<<<(B_ * N_) / 4, 256>>>(out);
}

// round 11
// speedup vs baseline: 1.0589x; 1.0544x over previous
#include <cuda_runtime.h>
#include <cuda_bf16.h>
#include <cstdint>

#define B_ 64
#define N_ 32
#define H_ 24
#define F_ 256

// ---------------- scratch ----------------
__device__ float g_QWq[(size_t)B_ * N_ * F_];              // [b][n][g]
__device__ float g_logits[(size_t)B_ * N_ * H_];           // [b][n][h]
__device__ float g_VWv[(size_t)B_ * N_ * H_ * F_];         // [b][n][h][g]

// ---------------- helpers ----------------
__device__ __forceinline__ uint32_t s2u(const void* p) {
    return (uint32_t)__cvta_generic_to_shared(p);
}
__device__ __forceinline__ void cpasync16(uint32_t dst, const void* src) {
    asm volatile("cp.async.cg.shared.global [%0], [%1], 16;" :: "r"(dst), "l"(src));
}
__device__ __forceinline__ void cpcommit() { asm volatile("cp.async.commit_group;"); }
__device__ __forceinline__ void cpwait1() { asm volatile("cp.async.wait_group 1;" ::: "memory"); }
__device__ __forceinline__ void cpwait0() { asm volatile("cp.async.wait_all;" ::: "memory"); }

__device__ __forceinline__ uint32_t bpack(float a, float b, float& ra, float& rb) {
    __nv_bfloat16 ha = __float2bfloat16(a), hb = __float2bfloat16(b);
    ra = a - __bfloat162float(ha);
    rb = b - __bfloat162float(hb);
    return (uint32_t)__bfloat16_as_ushort(ha) | ((uint32_t)__bfloat16_as_ushort(hb) << 16);
}
__device__ __forceinline__ uint32_t bpack1(float a, float b) {
    __nv_bfloat16 ha = __float2bfloat16(a), hb = __float2bfloat16(b);
    return (uint32_t)__bfloat16_as_ushort(ha) | ((uint32_t)__bfloat16_as_ushort(hb) << 16);
}
__device__ __forceinline__ uint2 lds64(uint32_t a) {
    uint2 r;
    asm volatile("ld.shared.v2.u32 {%0,%1}, [%2];" : "=r"(r.x), "=r"(r.y) : "r"(a));
    return r;
}
__device__ __forceinline__ void mma4(float* c, uint2 rA, uint2 rA8, uint2 b) {
    asm volatile("mma.sync.aligned.m16n8k16.row.col.f32.bf16.bf16.f32 "
                 "{%0,%1,%2,%3}, {%4,%5,%6,%7}, {%8,%9}, {%0,%1,%2,%3};"
                 : "+f"(c[0]), "+f"(c[1]), "+f"(c[2]), "+f"(c[3])
                 : "r"(rA.x), "r"(rA8.x), "r"(rA.y), "r"(rA8.y), "r"(b.x), "r"(b.y));
}

// smem offsets (bytes) — raw double-buffered, converted single-buffered
#define OFF_WRAW 0        // 2 x 16384 fp32 W chunk
#define OFF_ARAW 32768    // 2 x 4096  fp32 A chunk
#define OFF_WH   40960    // 8192: bf16 W hi [256 g][32B interleaved]
#define OFF_WL   49152    // 8192: bf16 W lo
#define OFF_AH   57344    // 2048: bf16 A hi [64 r][32B]
#define OFF_AL   59392    // 2048
#define SMEM_SZ  61440

// Core: C[64 b][256 g] = A[64x256] @ W[256x256]; P passes (K then V for k_kv).
// LOGITS && pass==0 -> logits epilogue (dot with g_QWq + bk); else gmem write (+bw).
template <int P, bool LOGITS>
__device__ __forceinline__ void proj_core(
    char* smk, uint32_t sb,
    const float* __restrict__ A0, const float* __restrict__ A1, long sA,
    const float* __restrict__ W0, const float* __restrict__ W1,
    const float* __restrict__ bkp,   // logits bias (pass0, LOGITS only)
    const float* __restrict__ bwp,   // write bias (last pass)
    float* __restrict__ ob, long pitch,
    int n, int h, float (*sred)[64])
{
    const int t = threadIdx.x;
    const int w = t >> 5, l = t & 31;
    const int mhalf = w >> 2, wq = w & 3;
    const int c = l & 3;
    const int rho = l >> 2;
    const uint32_t x = ((l >> 4) & 1) << 2;
    const uint32_t woff = (uint32_t)(((2 * c) ^ x) << 2);

    float acc[2][8][4];
    #pragma unroll
    for (int i = 0; i < 2; i++)
        #pragma unroll
        for (int j = 0; j < 8; j++)
            #pragma unroll
            for (int k = 0; k < 4; k++) acc[i][j][k] = 0.f;

    // prefetch chunk gc into raw buffer gc&1 (cp.async — stays out of registers)
    auto prefetch = [&](int gc) {
        const int pass = gc >> 4, cc = gc & 15, buf = gc & 1;
        const float* Wp = ((P == 1 || pass == 0) ? W0 : W1) + (size_t)cc * 16 * F_;
        const float* Ap = ((P == 1 || pass == 0) ? A0 : A1);
        uint32_t wd = sb + OFF_WRAW + buf * 16384;
        #pragma unroll
        for (int q = 0; q < 4; ++q)
            cpasync16(wd + q * 4096 + t * 16, Wp + q * 1024 + t * 4);
        const int r = t >> 2, q = t & 3;
        cpasync16(sb + OFF_ARAW + buf * 4096 + t * 16,
                  Ap + (long)r * sA + cc * 16 + q * 4);
        cpcommit();
    };

    prefetch(0);
    prefetch(1);

    #pragma unroll 1
    for (int gc = 0; gc < 16 * P; ++gc) {
        const int buf = gc & 1;
        if (gc + 1 < 16 * P) cpwait1(); else cpwait0();
        __syncthreads();   // publishes raw buf; guards converted tiles vs prev HMMA

        // ---- convert W chunk: wraw[f][g] -> WH/WL (interleaved, conflict-free) ----
        {
            const float* wr = (const float*)(smk + OFF_WRAW + buf * 16384);
            float v[16];
            #pragma unroll
            for (int f = 0; f < 16; ++f) v[f] = wr[f * 256 + t];
            uint32_t hi[8], lo[8];
            #pragma unroll
            for (int j = 0; j < 8; ++j) {
                float ra, rb;
                hi[j] = bpack(v[2 * j], v[2 * j + 1], ra, rb);
                lo[j] = bpack1(ra, rb);
            }
            const int s0 = ((t >> 2) & 1) << 4;
            char* bh = smk + OFF_WH + t * 32;
            char* bl = smk + OFF_WL + t * 32;
            *(uint4*)(bh + s0)        = make_uint4(hi[0], hi[4], hi[1], hi[5]);
            *(uint4*)(bh + (16 ^ s0)) = make_uint4(hi[2], hi[6], hi[3], hi[7]);
            *(uint4*)(bl + s0)        = make_uint4(lo[0], lo[4], lo[1], lo[5]);
            *(uint4*)(bl + (16 ^ s0)) = make_uint4(lo[2], lo[6], lo[3], lo[7]);
        }
        // ---- convert A chunk: araw[r][f] -> AH/AL ----
        {
            const int r = t >> 2, q = t & 3;
            float4 v = *(const float4*)(smk + OFF_ARAW + buf * 4096 + t * 16);
            float r0, r1, r2, r3;
            uint32_t h0 = bpack(v.x, v.y, r0, r1);
            uint32_t h1 = bpack(v.z, v.w, r2, r3);
            uint32_t l0 = bpack1(r0, r1);
            uint32_t l1 = bpack1(r2, r3);
            const int iw0 = (q < 2) ? 4 * q : 4 * q - 7;
            const int iw1 = (q < 2) ? 4 * q + 2 : 4 * q - 5;
            const int x4 = ((r >> 2) & 1) << 2;
            char* ah = smk + OFF_AH + r * 32;
            char* al = smk + OFF_AL + r * 32;
            *(uint32_t*)(ah + ((iw0 ^ x4) << 2)) = h0;
            *(uint32_t*)(ah + ((iw1 ^ x4) << 2)) = h1;
            *(uint32_t*)(al + ((iw0 ^ x4) << 2)) = l0;
            *(uint32_t*)(al + ((iw1 ^ x4) << 2)) = l1;
        }
        __syncthreads();

        if (gc + 2 < 16 * P) prefetch(gc + 2);

        // ---- A fragments hoisted once per chunk; nt-outer so W frags load once ----
        uint2 fa[2][4];
        #pragma unroll
        for (int mt = 0; mt < 2; ++mt) {
            const int r1 = mhalf * 32 + mt * 16 + rho;
            fa[mt][0] = lds64(sb + OFF_AH + r1 * 32 + woff);
            fa[mt][1] = lds64(sb + OFF_AH + (r1 + 8) * 32 + woff);
            fa[mt][2] = lds64(sb + OFF_AL + r1 * 32 + woff);
            fa[mt][3] = lds64(sb + OFF_AL + (r1 + 8) * 32 + woff);
        }
        #pragma unroll
        for (int nt = 0; nt < 8; ++nt) {
            const int g = wq * 64 + nt * 8 + rho;
            uint2 bh = lds64(sb + OFF_WH + g * 32 + woff);
            uint2 bl = lds64(sb + OFF_WL + g * 32 + woff);
            #pragma unroll
            for (int mt = 0; mt < 2; ++mt) {
                mma4(acc[mt][nt], fa[mt][0], fa[mt][1], bh);
                mma4(acc[mt][nt], fa[mt][0], fa[mt][1], bl);
                mma4(acc[mt][nt], fa[mt][2], fa[mt][3], bh);
            }
        }

        // ---- end-of-pass epilogues ----
        if ((gc & 15) == 15) {
            const int pass = gc >> 4;
            if (LOGITS && pass == 0) {
                // logits[b] = sum_g (C[b][g] + bk[g]) * QWq[b][n][g]
                float p[4] = {0.f, 0.f, 0.f, 0.f};
                #pragma unroll
                for (int nt = 0; nt < 8; ++nt) {
                    const int g0 = wq * 64 + nt * 8 + 2 * c;
                    const float2 bkv = *(const float2*)(bkp + g0);
                    #pragma unroll
                    for (int rr = 0; rr < 4; ++rr) {
                        const int row = mhalf * 32 + (rr >> 1) * 16 + (rr & 1) * 8 + rho;
                        const float2 qv = *(const float2*)(g_QWq + ((size_t)row * N_ + n) * F_ + g0);
                        p[rr] += (acc[rr >> 1][nt][(rr & 1) * 2]     + bkv.x) * qv.x
                               + (acc[rr >> 1][nt][(rr & 1) * 2 + 1] + bkv.y) * qv.y;
                    }
                }
                #pragma unroll
                for (int rr = 0; rr < 4; ++rr) {
                    p[rr] += __shfl_xor_sync(0xffffffffu, p[rr], 1);
                    p[rr] += __shfl_xor_sync(0xffffffffu, p[rr], 2);
                }
                if (c == 0) {
                    #pragma unroll
                    for (int rr = 0; rr < 4; ++rr)
                        sred[wq][mhalf * 32 + (rr >> 1) * 16 + (rr & 1) * 8 + rho] = p[rr];
                }
                __syncthreads();
                if (t < 64) {
                    float s = sred[0][t] + sred[1][t] + sred[2][t] + sred[3][t];
                    g_logits[((size_t)t * N_ + n) * H_ + h] = s;
                }
                #pragma unroll
                for (int i = 0; i < 2; i++)
                    #pragma unroll
                    for (int j = 0; j < 8; j++)
                        #pragma unroll
                        for (int k = 0; k < 4; k++) acc[i][j][k] = 0.f;
            } else {
                // gmem write (+ bias)
                #pragma unroll
                for (int nt = 0; nt < 8; ++nt) {
                    const int g0 = wq * 64 + nt * 8 + 2 * c;
                    const float2 bv2 = *(const float2*)(bwp + g0);
                    #pragma unroll
                    for (int mt = 0; mt < 2; ++mt) {
                        const int r1 = mhalf * 32 + mt * 16 + rho;
                        float2 v0, v1;
                        v0.x = acc[mt][nt][0] + bv2.x; v0.y = acc[mt][nt][1] + bv2.y;
                        v1.x = acc[mt][nt][2] + bv2.x; v1.y = acc[mt][nt][3] + bv2.y;
                        *(float2*)(ob + (long)r1 * pitch + g0) = v0;
                        *(float2*)(ob + (long)(r1 + 8) * pitch + g0) = v1;
                    }
                }
            }
        }
    }
}

// ---------------- kernels ----------------
__global__ void __launch_bounds__(256, 2) k_kv(const float* __restrict__ Kt,
                                               const float* __restrict__ Vt,
                                               const float* __restrict__ Wk,
                                               const float* __restrict__ bk,
                                               const float* __restrict__ Wv,
                                               const float* __restrict__ bv)
{
    extern __shared__ char smk[];
    __shared__ float sred[4][64];
    const int h = blockIdx.x, n = blockIdx.y;
    const size_t nh = (size_t)n * H_ + h;
    proj_core<2, true>(smk, s2u(smk),
                       Kt + ((size_t)h * N_ + n) * F_, Vt + ((size_t)h * N_ + n) * F_,
                       (long)H_ * N_ * F_,
                       Wk + nh * F_ * F_, Wv + nh * F_ * F_,
                       bk + nh * F_, bv + nh * F_,
                       g_VWv + nh * F_, (long)N_ * H_ * F_, n, h, sred);
}

__global__ void __launch_bounds__(256, 2) k_qwq(const float* __restrict__ Q,
                                                const float* __restrict__ Wq,
                                                const float* __restrict__ bq)
{
    extern __shared__ char smk[];
    __shared__ float sred[4][64];
    const int n = blockIdx.x;
    proj_core<1, false>(smk, s2u(smk),
                        Q + (size_t)n * F_, Q + (size_t)n * F_, (long)N_ * F_,
                        Wq + (size_t)n * F_ * F_, Wq + (size_t)n * F_ * F_,
                        bq + (size_t)n * F_, bq + (size_t)n * F_,
                        g_QWq + (size_t)n * F_, (long)N_ * F_, n, 0, sred);
}

// softmax over H; writes scores into out tail region
__global__ void k_softmax(float* __restrict__ out)
{
    const int idx = blockIdx.x * 256 + threadIdx.x;   // b*N+n
    const float* lp = g_logits + (size_t)idx * H_;
    float v[H_];
    float m = -3.4e38f;
    #pragma unroll
    for (int h = 0; h < H_; ++h) { v[h] = lp[h]; m = fmaxf(m, v[h]); }
    float s = 0.f;
    #pragma unroll
    for (int h = 0; h < H_; ++h) { v[h] = expf(v[h] - m); s += v[h]; }
    const float inv = 1.0f / s;
    float* sp = out + (size_t)B_ * N_ * F_ + (size_t)idx * H_;
    #pragma unroll
    for (int h = 0; h < H_; ++h) sp[h] = v[h] * inv;
}

// heads[b][n][g] = sum_h scores[b][n][h] * VWv[b][n][h][g]; 4 bn per CTA, float4
__global__ void __launch_bounds__(256) k_heads(float* __restrict__ out)
{
    __shared__ float s[4][H_];
    const int bn0 = blockIdx.x * 4;
    const int t = threadIdx.x;
    if (t < 4 * H_) {
        const int bl = t / H_, hh = t % H_;
        s[bl][hh] = out[(size_t)B_ * N_ * F_ + (size_t)(bn0 + bl) * H_ + hh];
    }
    __syncthreads();
    const int bl = t >> 6;
    const int gq = (t & 63) * 4;
    const float* vp = g_VWv + (size_t)(bn0 + bl) * H_ * F_ + gq;
    float4 a = make_float4(0.f, 0.f, 0.f, 0.f);
    #pragma unroll
    for (int h = 0; h < H_; ++h) {
        const float4 v = *(const float4*)(vp + (size_t)h * F_);
        const float sc = s[bl][h];
        a.x += sc * v.x; a.y += sc * v.y; a.z += sc * v.z; a.w += sc * v.w;
    }
    *(float4*)(out + (size_t)(bn0 + bl) * F_ + gq) = a;
}

// ---------------- launch ----------------
extern "C" void kernel_launch(void* const* d_in, const int* in_sizes, int n_in,
                              void* d_out, int out_size)
{
    (void)in_sizes; (void)n_in; (void)out_size;
    const float* Q  = (const float*)d_in[0];
    const float* K  = (const float*)d_in[1];
    const float* V  = (const float*)d_in[2];
    const float* Wq = (const float*)d_in[3];
    const float* bq = (const float*)d_in[4];
    const float* Wk = (const float*)d_in[5];
    const float* bk = (const float*)d_in[6];
    const float* Wv = (const float*)d_in[7];
    const float* bv = (const float*)d_in[8];
    float* out = (float*)d_out;

    // Raise the dynamic-smem cap ONCE, outside graph capture (the harness's
    // correctness call precedes capture). 61440 > default 48KB cap.
    static int attr_done = 0;
    if (!attr_done) {
        cudaFuncSetAttribute(k_kv, cudaFuncAttributeMaxDynamicSharedMemorySize, SMEM_SZ);
        cudaFuncSetAttribute(k_qwq, cudaFuncAttributeMaxDynamicSharedMemorySize, SMEM_SZ);
        attr_done = 1;
    }

    k_qwq<<<N_, 256, SMEM_SZ>>>(Q, Wq, bq);
    k_kv<<<dim3(H_, N_), 256, SMEM_SZ>>>(K, V, Wk, bk, Wv, bv);
    k_softmax<<<(B_ * N_) / 256, 256>>>(out);
    k_heads<<<(B_ * N_) / 4, 256>>>(out);
}

// round 14
// speedup vs baseline: 1.0775x; 1.0176x over previous
#include <cuda_runtime.h>
#include <cuda_bf16.h>
#include <cstdint>

#define B_ 64
#define N_ 32
#define H_ 24
#define F_ 256
#define BNF ((size_t)B_ * N_ * F_)

// ---------------- scratch ----------------
__device__ float g_QWq[(size_t)B_ * N_ * F_];              // [b][n][g]
__device__ float g_logits[(size_t)B_ * N_ * H_];           // [b][n][h]

// ---------------- helpers ----------------
__device__ __forceinline__ uint32_t s2u(const void* p) {
    return (uint32_t)__cvta_generic_to_shared(p);
}
__device__ __forceinline__ void cpasync16(uint32_t dst, const void* src) {
    asm volatile("cp.async.cg.shared.global [%0], [%1], 16;" :: "r"(dst), "l"(src));
}
__device__ __forceinline__ void cpcommit() { asm volatile("cp.async.commit_group;"); }
__device__ __forceinline__ void cpwait1() { asm volatile("cp.async.wait_group 1;" ::: "memory"); }
__device__ __forceinline__ void cpwait0() { asm volatile("cp.async.wait_all;" ::: "memory"); }

__device__ __forceinline__ uint32_t bpack(float a, float b, float& ra, float& rb) {
    __nv_bfloat16 ha = __float2bfloat16(a), hb = __float2bfloat16(b);
    ra = a - __bfloat162float(ha);
    rb = b - __bfloat162float(hb);
    return (uint32_t)__bfloat16_as_ushort(ha) | ((uint32_t)__bfloat16_as_ushort(hb) << 16);
}
__device__ __forceinline__ uint32_t bpack1(float a, float b) {
    __nv_bfloat16 ha = __float2bfloat16(a), hb = __float2bfloat16(b);
    return (uint32_t)__bfloat16_as_ushort(ha) | ((uint32_t)__bfloat16_as_ushort(hb) << 16);
}
__device__ __forceinline__ uint2 lds64(uint32_t a) {
    uint2 r;
    asm volatile("ld.shared.v2.u32 {%0,%1}, [%2];" : "=r"(r.x), "=r"(r.y) : "r"(a));
    return r;
}
__device__ __forceinline__ void mma4(float* c, uint2 rA, uint2 rA8, uint2 b) {
    asm volatile("mma.sync.aligned.m16n8k16.row.col.f32.bf16.bf16.f32 "
                 "{%0,%1,%2,%3}, {%4,%5,%6,%7}, {%8,%9}, {%0,%1,%2,%3};"
                 : "+f"(c[0]), "+f"(c[1]), "+f"(c[2]), "+f"(c[3])
                 : "r"(rA.x), "r"(rA8.x), "r"(rA.y), "r"(rA8.y), "r"(b.x), "r"(b.y));
}

// smem offsets — raw double-buffered, converted single-buffered
#define OFF_WRAW 0        // 2 x 16384 fp32 W chunk
#define OFF_ARAW 32768    // 2 x 4096  fp32 A chunk
#define OFF_WH   40960    // 8192
#define OFF_WL   49152    // 8192
#define OFF_AH   57344    // 2048
#define OFF_AL   59392    // 2048
#define SMEM_SZ  61440

// MODE: 0 = plain write (+bias), 1 = per-h logits, 2 = score-scaled A + atomic red
template <int HG, int MODE>
__device__ __forceinline__ void proj_run(
    char* smk, uint32_t sb,
    const float* __restrict__ Ab, long aRow, size_t aH,
    const float* __restrict__ Wb, size_t wH,
    const float* __restrict__ biasb, size_t biasH,
    float* __restrict__ outp, long pitch,
    int n, int hg,
    float (*sred)[64], float* sextra, float* sbv)
{
    const int t = threadIdx.x;
    const int w = t >> 5, l = t & 31;
    const int mhalf = w >> 2, wq = w & 3;
    const int c = l & 3;
    const int rho = l >> 2;
    const uint32_t x = ((l >> 4) & 1) << 2;
    const uint32_t woff = (uint32_t)(((2 * c) ^ x) << 2);
    const int NC = 16 * HG;

    float acc[2][8][4];
    #pragma unroll
    for (int i = 0; i < 2; i++)
        #pragma unroll
        for (int j = 0; j < 8; j++)
            #pragma unroll
            for (int k = 0; k < 4; k++) acc[i][j][k] = 0.f;

    const int ar = t >> 2, aq = t & 3;

    auto prefetch = [&](int gc) {
        const int hx = gc >> 4, cc = gc & 15, buf = gc & 1;
        const float* Wp = Wb + (size_t)hx * wH + (size_t)cc * 16 * F_;
        uint32_t wd = sb + OFF_WRAW + buf * 16384;
        #pragma unroll
        for (int q = 0; q < 4; ++q)
            cpasync16(wd + q * 4096 + t * 16, Wp + q * 1024 + t * 4);
        cpasync16(sb + OFF_ARAW + buf * 4096 + t * 16,
                  Ab + (size_t)hx * aH + (long)ar * aRow + cc * 16 + aq * 4);
        cpcommit();
    };

    prefetch(0);
    prefetch(1);

    // MODE2: stage scores (sextra[3][64]) and bias rows (sbv[3][256])
    if (MODE == 2) {
        if (t < HG * 64) {
            const int i = t >> 6, b = t & 63;
            sextra[i * 64 + b] = outp[BNF + ((size_t)b * N_ + n) * H_ + hg * HG + i];
        }
        #pragma unroll
        for (int i = 0; i < HG; ++i)
            sbv[i * 256 + t] = biasb[(size_t)i * biasH + t];
    }

    #pragma unroll 1
    for (int gc = 0; gc < NC; ++gc) {
        const int buf = gc & 1;
        if (gc + 1 < NC) cpwait1(); else cpwait0();
        __syncthreads();

        // ---- convert W: wraw[f][g] -> WH/WL ----
        {
            const float* wr = (const float*)(smk + OFF_WRAW + buf * 16384);
            float v[16];
            #pragma unroll
            for (int f = 0; f < 16; ++f) v[f] = wr[f * 256 + t];
            uint32_t hi[8], lo[8];
            #pragma unroll
            for (int j = 0; j < 8; ++j) {
                float ra, rb;
                hi[j] = bpack(v[2 * j], v[2 * j + 1], ra, rb);
                lo[j] = bpack1(ra, rb);
            }
            const int s0 = ((t >> 2) & 1) << 4;
            char* bh = smk + OFF_WH + t * 32;
            char* bl = smk + OFF_WL + t * 32;
            *(uint4*)(bh + s0)        = make_uint4(hi[0], hi[4], hi[1], hi[5]);
            *(uint4*)(bh + (16 ^ s0)) = make_uint4(hi[2], hi[6], hi[3], hi[7]);
            *(uint4*)(bl + s0)        = make_uint4(lo[0], lo[4], lo[1], lo[5]);
            *(uint4*)(bl + (16 ^ s0)) = make_uint4(lo[2], lo[6], lo[3], lo[7]);
        }
        // ---- convert A (MODE2: rows pre-scaled by softmax score) ----
        {
            float4 v = *(const float4*)(smk + OFF_ARAW + buf * 4096 + t * 16);
            if (MODE == 2) {
                const float sc = sextra[(gc >> 4) * 64 + ar];
                v.x *= sc; v.y *= sc; v.z *= sc; v.w *= sc;
            }
            float r0, r1, r2, r3;
            uint32_t h0 = bpack(v.x, v.y, r0, r1);
            uint32_t h1 = bpack(v.z, v.w, r2, r3);
            uint32_t l0 = bpack1(r0, r1);
            uint32_t l1 = bpack1(r2, r3);
            const int iw0 = (aq < 2) ? 4 * aq : 4 * aq - 7;
            const int iw1 = (aq < 2) ? 4 * aq + 2 : 4 * aq - 5;
            const int x4 = ((ar >> 2) & 1) << 2;
            char* ah = smk + OFF_AH + ar * 32;
            char* al = smk + OFF_AL + ar * 32;
            *(uint32_t*)(ah + ((iw0 ^ x4) << 2)) = h0;
            *(uint32_t*)(ah + ((iw1 ^ x4) << 2)) = h1;
            *(uint32_t*)(al + ((iw0 ^ x4) << 2)) = l0;
            *(uint32_t*)(al + ((iw1 ^ x4) << 2)) = l1;
        }
        __syncthreads();

        if (gc + 2 < NC) prefetch(gc + 2);

        // ---- fragments + HMMA (nt-outer) ----
        uint2 fa[2][4];
        #pragma unroll
        for (int mt = 0; mt < 2; ++mt) {
            const int r1 = mhalf * 32 + mt * 16 + rho;
            fa[mt][0] = lds64(sb + OFF_AH + r1 * 32 + woff);
            fa[mt][1] = lds64(sb + OFF_AH + (r1 + 8) * 32 + woff);
            fa[mt][2] = lds64(sb + OFF_AL + r1 * 32 + woff);
            fa[mt][3] = lds64(sb + OFF_AL + (r1 + 8) * 32 + woff);
        }
        #pragma unroll
        for (int nt = 0; nt < 8; ++nt) {
            const int g = wq * 64 + nt * 8 + rho;
            uint2 bh = lds64(sb + OFF_WH + g * 32 + woff);
            uint2 bl = lds64(sb + OFF_WL + g * 32 + woff);
            #pragma unroll
            for (int mt = 0; mt < 2; ++mt) {
                mma4(acc[mt][nt], fa[mt][0], fa[mt][1], bh);
                mma4(acc[mt][nt], fa[mt][0], fa[mt][1], bl);
                mma4(acc[mt][nt], fa[mt][2], fa[mt][3], bh);
            }
        }

        // ---- epilogues ----
        if (MODE == 1 && (gc & 15) == 15) {
            const int hx = gc >> 4;
            const int h = hg * HG + hx;
            const float* bkp = biasb + (size_t)hx * biasH;
            float p[4] = {0.f, 0.f, 0.f, 0.f};
            #pragma unroll
            for (int nt = 0; nt < 8; ++nt) {
                const int g0 = wq * 64 + nt * 8 + 2 * c;
                const float2 bkv = *(const float2*)(bkp + g0);
                #pragma unroll
                for (int rr = 0; rr < 4; ++rr) {
                    const int row = mhalf * 32 + (rr >> 1) * 16 + (rr & 1) * 8 + rho;
                    const float2 qv = *(const float2*)(g_QWq + ((size_t)row * N_ + n) * F_ + g0);
                    p[rr] += (acc[rr >> 1][nt][(rr & 1) * 2]     + bkv.x) * qv.x
                           + (acc[rr >> 1][nt][(rr & 1) * 2 + 1] + bkv.y) * qv.y;
                }
            }
            #pragma unroll
            for (int rr = 0; rr < 4; ++rr) {
                p[rr] += __shfl_xor_sync(0xffffffffu, p[rr], 1);
                p[rr] += __shfl_xor_sync(0xffffffffu, p[rr], 2);
            }
            if (c == 0) {
                #pragma unroll
                for (int rr = 0; rr < 4; ++rr)
                    sred[wq][mhalf * 32 + (rr >> 1) * 16 + (rr & 1) * 8 + rho] = p[rr];
            }
            __syncthreads();
            if (t < 64)
                g_logits[((size_t)t * N_ + n) * H_ + h]
                    = sred[0][t] + sred[1][t] + sred[2][t] + sred[3][t];
            #pragma unroll
            for (int i = 0; i < 2; i++)
                #pragma unroll
                for (int j = 0; j < 8; j++)
                    #pragma unroll
                    for (int k = 0; k < 4; k++) acc[i][j][k] = 0.f;
        }
        if (MODE == 0 && gc == NC - 1) {
            #pragma unroll
            for (int nt = 0; nt < 8; ++nt) {
                const int g0 = wq * 64 + nt * 8 + 2 * c;
                const float2 bv2 = *(const float2*)(biasb + g0);
                #pragma unroll
                for (int mt = 0; mt < 2; ++mt) {
                    const int r1 = mhalf * 32 + mt * 16 + rho;
                    float2 v0, v1;
                    v0.x = acc[mt][nt][0] + bv2.x; v0.y = acc[mt][nt][1] + bv2.y;
                    v1.x = acc[mt][nt][2] + bv2.x; v1.y = acc[mt][nt][3] + bv2.y;
                    *(float2*)(outp + (long)r1 * pitch + g0) = v0;
                    *(float2*)(outp + (long)(r1 + 8) * pitch + g0) = v1;
                }
            }
        }
        if (MODE == 2 && gc == NC - 1) {
            // heads += acc + sum_i s_i * bv_i  (atomic; out region is L2-resident)
            float sA[2][HG], sB[2][HG];   // scores for rows r1 and r1+8, per mt
            #pragma unroll
            for (int mt = 0; mt < 2; ++mt) {
                const int r1 = mhalf * 32 + mt * 16 + rho;
                #pragma unroll
                for (int i = 0; i < HG; ++i) {
                    sA[mt][i] = sextra[i * 64 + r1];
                    sB[mt][i] = sextra[i * 64 + r1 + 8];
                }
            }
            #pragma unroll
            for (int nt = 0; nt < 8; ++nt) {
                const int g0 = wq * 64 + nt * 8 + 2 * c;
                float bx[HG], by[HG];
                #pragma unroll
                for (int i = 0; i < HG; ++i) {
                    bx[i] = sbv[i * 256 + g0];
                    by[i] = sbv[i * 256 + g0 + 1];
                }
                #pragma unroll
                for (int mt = 0; mt < 2; ++mt) {
                    const int r1 = mhalf * 32 + mt * 16 + rho;
                    float vx = acc[mt][nt][0], vy = acc[mt][nt][1];
                    float wx = acc[mt][nt][2], wy = acc[mt][nt][3];
                    #pragma unroll
                    for (int i = 0; i < HG; ++i) {
                        vx += sA[mt][i] * bx[i]; vy += sA[mt][i] * by[i];
                        wx += sB[mt][i] * bx[i]; wy += sB[mt][i] * by[i];
                    }
                    float* o0 = outp + ((size_t)r1 * N_ + n) * F_ + g0;
                    float* o1 = outp + ((size_t)(r1 + 8) * N_ + n) * F_ + g0;
                    atomicAdd(o0, vx);     atomicAdd(o0 + 1, vy);
                    atomicAdd(o1, wx);     atomicAdd(o1 + 1, wy);
                }
            }
        }
    }
}

// ---------------- kernels ----------------
__global__ void __launch_bounds__(256, 2) k_qwq(const float* __restrict__ Q,
                                                const float* __restrict__ Wq,
                                                const float* __restrict__ bq)
{
    extern __shared__ char smk[];
    const int n = blockIdx.x;
    proj_run<1, 0>(smk, s2u(smk),
                   Q + (size_t)n * F_, (long)N_ * F_, 0,
                   Wq + (size_t)n * F_ * F_, 0,
                   bq + (size_t)n * F_, 0,
                   g_QWq + (size_t)n * F_, (long)N_ * F_,
                   n, 0, nullptr, nullptr, nullptr);
}

__global__ void __launch_bounds__(256, 2) k_klogits(const float* __restrict__ Kt,
                                                    const float* __restrict__ Wk,
                                                    const float* __restrict__ bk)
{
    extern __shared__ char smk[];
    __shared__ float sred[4][64];
    const int hg = blockIdx.x, n = blockIdx.y;
    const size_t nh0 = (size_t)n * H_ + hg * 3;
    proj_run<3, 1>(smk, s2u(smk),
                   Kt + ((size_t)(hg * 3) * N_ + n) * F_, (long)H_ * N_ * F_, (size_t)N_ * F_,
                   Wk + nh0 * F_ * F_, (size_t)F_ * F_,
                   bk + nh0 * F_, F_,
                   nullptr, 0, n, hg, sred, nullptr, nullptr);
}

__global__ void __launch_bounds__(256, 2) k_vheads(const float* __restrict__ Vt,
                                                   const float* __restrict__ Wv,
                                                   const float* __restrict__ bv,
                                                   float* __restrict__ out)
{
    extern __shared__ char smk[];
    __shared__ float sextra[3 * 64];
    __shared__ float sbv[3 * 256];
    const int hg = blockIdx.x, n = blockIdx.y;
    const size_t nh0 = (size_t)n * H_ + hg * 3;
    proj_run<3, 2>(smk, s2u(smk),
                   Vt + ((size_t)(hg * 3) * N_ + n) * F_, (long)H_ * N_ * F_, (size_t)N_ * F_,
                   Wv + nh0 * F_ * F_, (size_t)F_ * F_,
                   bv + nh0 * F_, F_,
                   out, 0, n, hg, nullptr, sextra, sbv);
}

__global__ void k_zero(float* __restrict__ out)
{
    const size_t i = (size_t)blockIdx.x * 256 + threadIdx.x;
    *(float4*)(out + i * 4) = make_float4(0.f, 0.f, 0.f, 0.f);
}

__global__ void k_softmax(float* __restrict__ out)
{
    const int idx = blockIdx.x * 256 + threadIdx.x;   // b*N+n
    const float* lp = g_logits + (size_t)idx * H_;
    float v[H_];
    float m = -3.4e38f;
    #pragma unroll
    for (int h = 0; h < H_; ++h) { v[h] = lp[h]; m = fmaxf(m, v[h]); }
    float s = 0.f;
    #pragma unroll
    for (int h = 0; h < H_; ++h) { v[h] = expf(v[h] - m); s += v[h]; }
    const float inv = 1.0f / s;
    float* sp = out + BNF + (size_t)idx * H_;
    #pragma unroll
    for (int h = 0; h < H_; ++h) sp[h] = v[h] * inv;
}

// ---------------- launch ----------------
extern "C" void kernel_launch(void* const* d_in, const int* in_sizes, int n_in,
                              void* d_out, int out_size)
{
    (void)in_sizes; (void)n_in; (void)out_size;
    const float* Q  = (const float*)d_in[0];
    const float* K  = (const float*)d_in[1];
    const float* V  = (const float*)d_in[2];
    const float* Wq = (const float*)d_in[3];
    const float* bq = (const float*)d_in[4];
    const float* Wk = (const float*)d_in[5];
    const float* bk = (const float*)d_in[6];
    const float* Wv = (const float*)d_in[7];
    const float* bv = (const float*)d_in[8];
    float* out = (float*)d_out;

    // Raise dynamic-smem cap once, outside graph capture (correctness run first).
    static int attr_done = 0;
    if (!attr_done) {
        cudaFuncSetAttribute(k_qwq,     cudaFuncAttributeMaxDynamicSharedMemorySize, SMEM_SZ);
        cudaFuncSetAttribute(k_klogits, cudaFuncAttributeMaxDynamicSharedMemorySize, SMEM_SZ);
        cudaFuncSetAttribute(k_vheads,  cudaFuncAttributeMaxDynamicSharedMemorySize, SMEM_SZ);
        attr_done = 1;
    }

    k_zero<<<(B_ * N_ * F_) / 1024, 256>>>(out);                 // zero heads region
    k_qwq<<<N_, 256, SMEM_SZ>>>(Q, Wq, bq);
    k_klogits<<<dim3(H_ / 3, N_), 256, SMEM_SZ>>>(K, Wk, bk);
    k_softmax<<<(B_ * N_) / 256, 256>>>(out);
    k_vheads<<<dim3(H_ / 3, N_), 256, SMEM_SZ>>>(V, Wv, bv, out);
}

// round 15
// speedup vs baseline: 1.1365x; 1.0547x over previous
#include <cuda_runtime.h>
#include <cuda_bf16.h>
#include <cstdint>

#define B_ 64
#define N_ 32
#define H_ 24
#define F_ 256
#define BNF ((size_t)B_ * N_ * F_)

// ---------------- scratch ----------------
__device__ float g_QWq[(size_t)B_ * N_ * F_];              // [b][n][g]
__device__ float g_logits[(size_t)B_ * N_ * H_];           // [b][n][h]

// ---------------- helpers ----------------
__device__ __forceinline__ uint32_t s2u(const void* p) {
    return (uint32_t)__cvta_generic_to_shared(p);
}
__device__ __forceinline__ void cpasync16(uint32_t dst, const void* src) {
    asm volatile("cp.async.cg.shared.global [%0], [%1], 16;" :: "r"(dst), "l"(src));
}
__device__ __forceinline__ void cpcommit() { asm volatile("cp.async.commit_group;"); }
__device__ __forceinline__ void cpwait1() { asm volatile("cp.async.wait_group 1;" ::: "memory"); }
__device__ __forceinline__ void cpwait0() { asm volatile("cp.async.wait_all;" ::: "memory"); }

__device__ __forceinline__ uint32_t bpack(float a, float b, float& ra, float& rb) {
    __nv_bfloat16 ha = __float2bfloat16(a), hb = __float2bfloat16(b);
    ra = a - __bfloat162float(ha);
    rb = b - __bfloat162float(hb);
    return (uint32_t)__bfloat16_as_ushort(ha) | ((uint32_t)__bfloat16_as_ushort(hb) << 16);
}
__device__ __forceinline__ uint32_t bpack1(float a, float b) {
    __nv_bfloat16 ha = __float2bfloat16(a), hb = __float2bfloat16(b);
    return (uint32_t)__bfloat16_as_ushort(ha) | ((uint32_t)__bfloat16_as_ushort(hb) << 16);
}
__device__ __forceinline__ uint2 lds64(uint32_t a) {
    uint2 r;
    asm volatile("ld.shared.v2.u32 {%0,%1}, [%2];" : "=r"(r.x), "=r"(r.y) : "r"(a));
    return r;
}
__device__ __forceinline__ void mma4(float* c, uint2 rA, uint2 rA8, uint2 b) {
    asm volatile("mma.sync.aligned.m16n8k16.row.col.f32.bf16.bf16.f32 "
                 "{%0,%1,%2,%3}, {%4,%5,%6,%7}, {%8,%9}, {%0,%1,%2,%3};"
                 : "+f"(c[0]), "+f"(c[1]), "+f"(c[2]), "+f"(c[3])
                 : "r"(rA.x), "r"(rA8.x), "r"(rA.y), "r"(rA8.y), "r"(b.x), "r"(b.y));
}

// smem: raw double-buffered AND converted double-buffered (pipelined)
#define OFF_WRAW 0        // 2 x 16384 fp32 W chunk
#define OFF_ARAW 32768    // 2 x 4096  fp32 A chunk
#define OFF_CB   40960    // 2 x 20480 converted: WH@0, WL@8192, AH@16384, AL@18432
#define CBSZ     20480
#define SMEM_SZ  81920

// MODE: 0 = plain write (+bias), 1 = per-h logits, 2 = score-scaled A + atomic red
template <int HG, int MODE>
__device__ __forceinline__ void proj_run(
    char* smk, uint32_t sb,
    const float* __restrict__ Ab, long aRow, size_t aH,
    const float* __restrict__ Wb, size_t wH,
    const float* __restrict__ biasb, size_t biasH,
    float* __restrict__ outp, long pitch,
    int n, int hg,
    float (*sred)[64], float* sextra, float* sbv)
{
    const int t = threadIdx.x;
    const int w = t >> 5, l = t & 31;
    const int mhalf = w >> 2, wq = w & 3;
    const int c = l & 3;
    const int rho = l >> 2;
    const uint32_t x = ((l >> 4) & 1) << 2;
    const uint32_t woff = (uint32_t)(((2 * c) ^ x) << 2);
    const int NC = 16 * HG;

    float acc[2][8][4];
    #pragma unroll
    for (int i = 0; i < 2; i++)
        #pragma unroll
        for (int j = 0; j < 8; j++)
            #pragma unroll
            for (int k = 0; k < 4; k++) acc[i][j][k] = 0.f;

    const int ar = t >> 2, aq = t & 3;

    auto prefetch = [&](int gc) {
        const int hx = gc >> 4, cc = gc & 15, buf = gc & 1;
        const float* Wp = Wb + (size_t)hx * wH + (size_t)cc * 16 * F_;
        uint32_t wd = sb + OFF_WRAW + buf * 16384;
        #pragma unroll
        for (int q = 0; q < 4; ++q)
            cpasync16(wd + q * 4096 + t * 16, Wp + q * 1024 + t * 4);
        cpasync16(sb + OFF_ARAW + buf * 4096 + t * 16,
                  Ab + (size_t)hx * aH + (long)ar * aRow + cc * 16 + aq * 4);
        cpcommit();
    };

    // convert raw chunk ch -> cbuf[ch&1] (fma/alu pipe work)
    auto convert = [&](int ch) {
        const int buf = ch & 1;
        char* cbp = smk + OFF_CB + buf * CBSZ;
        // W: wraw[f][g] -> WH/WL interleaved (conflict-free)
        {
            const float* wr = (const float*)(smk + OFF_WRAW + buf * 16384);
            float v[16];
            #pragma unroll
            for (int f = 0; f < 16; ++f) v[f] = wr[f * 256 + t];
            uint32_t hi[8], lo[8];
            #pragma unroll
            for (int j = 0; j < 8; ++j) {
                float ra, rb;
                hi[j] = bpack(v[2 * j], v[2 * j + 1], ra, rb);
                lo[j] = bpack1(ra, rb);
            }
            const int s0 = ((t >> 2) & 1) << 4;
            char* bh = cbp + t * 32;
            char* bl = cbp + 8192 + t * 32;
            *(uint4*)(bh + s0)        = make_uint4(hi[0], hi[4], hi[1], hi[5]);
            *(uint4*)(bh + (16 ^ s0)) = make_uint4(hi[2], hi[6], hi[3], hi[7]);
            *(uint4*)(bl + s0)        = make_uint4(lo[0], lo[4], lo[1], lo[5]);
            *(uint4*)(bl + (16 ^ s0)) = make_uint4(lo[2], lo[6], lo[3], lo[7]);
        }
        // A (MODE2: rows pre-scaled by softmax score of this chunk's h)
        {
            float4 v = *(const float4*)(smk + OFF_ARAW + buf * 4096 + t * 16);
            if (MODE == 2) {
                const float sc = sextra[(ch >> 4) * 64 + ar];
                v.x *= sc; v.y *= sc; v.z *= sc; v.w *= sc;
            }
            float r0, r1, r2, r3;
            uint32_t h0 = bpack(v.x, v.y, r0, r1);
            uint32_t h1 = bpack(v.z, v.w, r2, r3);
            uint32_t l0 = bpack1(r0, r1);
            uint32_t l1 = bpack1(r2, r3);
            const int iw0 = (aq < 2) ? 4 * aq : 4 * aq - 7;
            const int iw1 = (aq < 2) ? 4 * aq + 2 : 4 * aq - 5;
            const int x4 = ((ar >> 2) & 1) << 2;
            char* ah = cbp + 16384 + ar * 32;
            char* al = cbp + 18432 + ar * 32;
            *(uint32_t*)(ah + ((iw0 ^ x4) << 2)) = h0;
            *(uint32_t*)(ah + ((iw1 ^ x4) << 2)) = h1;
            *(uint32_t*)(al + ((iw0 ^ x4) << 2)) = l0;
            *(uint32_t*)(al + ((iw1 ^ x4) << 2)) = l1;
        }
    };

    prefetch(0);
    prefetch(1);

    // MODE2: stage scores (sextra[HG][64]) and bias rows (sbv[HG][256])
    if (MODE == 2) {
        if (t < HG * 64) {
            const int i = t >> 6, b = t & 63;
            sextra[i * 64 + b] = outp[BNF + ((size_t)b * N_ + n) * H_ + hg * HG + i];
        }
        #pragma unroll
        for (int i = 0; i < HG; ++i)
            sbv[i * 256 + t] = biasb[(size_t)i * biasH + t];
    }

    cpwait1();            // raw chunk 0 complete (own thread)
    __syncthreads();      // publish raw0 + MODE2 staging
    convert(0);

    #pragma unroll 1
    for (int gc = 0; gc < NC; ++gc) {
        if (gc + 2 < NC) prefetch(gc + 2);
        if (gc + 1 < NC) { if (gc + 2 < NC) cpwait1(); else cpwait0(); }
        __syncthreads();  // publish cbuf[gc&1] (converted last iter) + raw gc+1

        // convert NEXT chunk (fma pipe) — overlaps with this chunk's MMAs (tensor pipe)
        if (gc + 1 < NC) convert(gc + 1);

        // ---- fragments + HMMA on cbuf[gc&1] (nt-outer) ----
        const uint32_t cb = sb + OFF_CB + (uint32_t)(gc & 1) * CBSZ;
        uint2 fa[2][4];
        #pragma unroll
        for (int mt = 0; mt < 2; ++mt) {
            const int r1 = mhalf * 32 + mt * 16 + rho;
            fa[mt][0] = lds64(cb + 16384 + r1 * 32 + woff);
            fa[mt][1] = lds64(cb + 16384 + (r1 + 8) * 32 + woff);
            fa[mt][2] = lds64(cb + 18432 + r1 * 32 + woff);
            fa[mt][3] = lds64(cb + 18432 + (r1 + 8) * 32 + woff);
        }
        #pragma unroll
        for (int nt = 0; nt < 8; ++nt) {
            const int g = wq * 64 + nt * 8 + rho;
            uint2 bh = lds64(cb + g * 32 + woff);
            uint2 bl = lds64(cb + 8192 + g * 32 + woff);
            #pragma unroll
            for (int mt = 0; mt < 2; ++mt) {
                mma4(acc[mt][nt], fa[mt][0], fa[mt][1], bh);
                mma4(acc[mt][nt], fa[mt][0], fa[mt][1], bl);
                mma4(acc[mt][nt], fa[mt][2], fa[mt][3], bh);
            }
        }

        // ---- epilogues ----
        if (MODE == 1 && (gc & 15) == 15) {
            const int hx = gc >> 4;
            const int h = hg * HG + hx;
            const float* bkp = biasb + (size_t)hx * biasH;
            float p[4] = {0.f, 0.f, 0.f, 0.f};
            #pragma unroll
            for (int nt = 0; nt < 8; ++nt) {
                const int g0 = wq * 64 + nt * 8 + 2 * c;
                const float2 bkv = *(const float2*)(bkp + g0);
                #pragma unroll
                for (int rr = 0; rr < 4; ++rr) {
                    const int row = mhalf * 32 + (rr >> 1) * 16 + (rr & 1) * 8 + rho;
                    const float2 qv = *(const float2*)(g_QWq + ((size_t)row * N_ + n) * F_ + g0);
                    p[rr] += (acc[rr >> 1][nt][(rr & 1) * 2]     + bkv.x) * qv.x
                           + (acc[rr >> 1][nt][(rr & 1) * 2 + 1] + bkv.y) * qv.y;
                }
            }
            #pragma unroll
            for (int rr = 0; rr < 4; ++rr) {
                p[rr] += __shfl_xor_sync(0xffffffffu, p[rr], 1);
                p[rr] += __shfl_xor_sync(0xffffffffu, p[rr], 2);
            }
            if (c == 0) {
                #pragma unroll
                for (int rr = 0; rr < 4; ++rr)
                    sred[wq][mhalf * 32 + (rr >> 1) * 16 + (rr & 1) * 8 + rho] = p[rr];
            }
            __syncthreads();
            if (t < 64)
                g_logits[((size_t)t * N_ + n) * H_ + h]
                    = sred[0][t] + sred[1][t] + sred[2][t] + sred[3][t];
            #pragma unroll
            for (int i = 0; i < 2; i++)
                #pragma unroll
                for (int j = 0; j < 8; j++)
                    #pragma unroll
                    for (int k = 0; k < 4; k++) acc[i][j][k] = 0.f;
        }
        if (MODE == 0 && gc == NC - 1) {
            #pragma unroll
            for (int nt = 0; nt < 8; ++nt) {
                const int g0 = wq * 64 + nt * 8 + 2 * c;
                const float2 bv2 = *(const float2*)(biasb + g0);
                #pragma unroll
                for (int mt = 0; mt < 2; ++mt) {
                    const int r1 = mhalf * 32 + mt * 16 + rho;
                    float2 v0, v1;
                    v0.x = acc[mt][nt][0] + bv2.x; v0.y = acc[mt][nt][1] + bv2.y;
                    v1.x = acc[mt][nt][2] + bv2.x; v1.y = acc[mt][nt][3] + bv2.y;
                    *(float2*)(outp + (long)r1 * pitch + g0) = v0;
                    *(float2*)(outp + (long)(r1 + 8) * pitch + g0) = v1;
                }
            }
        }
        if (MODE == 2 && gc == NC - 1) {
            float sA[2][HG], sB[2][HG];
            #pragma unroll
            for (int mt = 0; mt < 2; ++mt) {
                const int r1 = mhalf * 32 + mt * 16 + rho;
                #pragma unroll
                for (int i = 0; i < HG; ++i) {
                    sA[mt][i] = sextra[i * 64 + r1];
                    sB[mt][i] = sextra[i * 64 + r1 + 8];
                }
            }
            #pragma unroll
            for (int nt = 0; nt < 8; ++nt) {
                const int g0 = wq * 64 + nt * 8 + 2 * c;
                float bx[HG], by[HG];
                #pragma unroll
                for (int i = 0; i < HG; ++i) {
                    bx[i] = sbv[i * 256 + g0];
                    by[i] = sbv[i * 256 + g0 + 1];
                }
                #pragma unroll
                for (int mt = 0; mt < 2; ++mt) {
                    const int r1 = mhalf * 32 + mt * 16 + rho;
                    float vx = acc[mt][nt][0], vy = acc[mt][nt][1];
                    float wx = acc[mt][nt][2], wy = acc[mt][nt][3];
                    #pragma unroll
                    for (int i = 0; i < HG; ++i) {
                        vx += sA[mt][i] * bx[i]; vy += sA[mt][i] * by[i];
                        wx += sB[mt][i] * bx[i]; wy += sB[mt][i] * by[i];
                    }
                    float* o0 = outp + ((size_t)r1 * N_ + n) * F_ + g0;
                    float* o1 = outp + ((size_t)(r1 + 8) * N_ + n) * F_ + g0;
                    atomicAdd(o0, vx);     atomicAdd(o0 + 1, vy);
                    atomicAdd(o1, wx);     atomicAdd(o1 + 1, wy);
                }
            }
        }
        __syncthreads();   // cbuf[gc&1]/raw reuse guard
    }
}

// ---------------- kernels ----------------
__global__ void __launch_bounds__(256, 2) k_qwq(const float* __restrict__ Q,
                                                const float* __restrict__ Wq,
                                                const float* __restrict__ bq)
{
    extern __shared__ char smk[];
    const int n = blockIdx.x;
    proj_run<1, 0>(smk, s2u(smk),
                   Q + (size_t)n * F_, (long)N_ * F_, 0,
                   Wq + (size_t)n * F_ * F_, 0,
                   bq + (size_t)n * F_, 0,
                   g_QWq + (size_t)n * F_, (long)N_ * F_,
                   n, 0, nullptr, nullptr, nullptr);
}

__global__ void __launch_bounds__(256, 2) k_klogits(const float* __restrict__ Kt,
                                                    const float* __restrict__ Wk,
                                                    const float* __restrict__ bk)
{
    extern __shared__ char smk[];
    __shared__ float sred[4][64];
    const int hg = blockIdx.x, n = blockIdx.y;
    const size_t nh0 = (size_t)n * H_ + hg * 3;
    proj_run<3, 1>(smk, s2u(smk),
                   Kt + ((size_t)(hg * 3) * N_ + n) * F_, (long)H_ * N_ * F_, (size_t)N_ * F_,
                   Wk + nh0 * F_ * F_, (size_t)F_ * F_,
                   bk + nh0 * F_, F_,
                   nullptr, 0, n, hg, sred, nullptr, nullptr);
}

__global__ void __launch_bounds__(256, 2) k_vheads(const float* __restrict__ Vt,
                                                   const float* __restrict__ Wv,
                                                   const float* __restrict__ bv,
                                                   float* __restrict__ out)
{
    extern __shared__ char smk[];
    __shared__ float sextra[3 * 64];
    __shared__ float sbv[3 * 256];
    const int hg = blockIdx.x, n = blockIdx.y;
    const size_t nh0 = (size_t)n * H_ + hg * 3;
    proj_run<3, 2>(smk, s2u(smk),
                   Vt + ((size_t)(hg * 3) * N_ + n) * F_, (long)H_ * N_ * F_, (size_t)N_ * F_,
                   Wv + nh0 * F_ * F_, (size_t)F_ * F_,
                   bv + nh0 * F_, F_,
                   out, 0, n, hg, nullptr, sextra, sbv);
}

__global__ void k_zero(float* __restrict__ out)
{
    const size_t i = (size_t)blockIdx.x * 256 + threadIdx.x;
    *(float4*)(out + i * 4) = make_float4(0.f, 0.f, 0.f, 0.f);
}

// softmax: one warp per (b,n) row
__global__ void __launch_bounds__(256) k_softmax(float* __restrict__ out)
{
    const int wid = (blockIdx.x * 256 + threadIdx.x) >> 5;   // 0..2047 = b*N+n
    const int l = threadIdx.x & 31;
    float v = (l < H_) ? g_logits[(size_t)wid * H_ + l] : -3.4e38f;
    float m = v;
    #pragma unroll
    for (int off = 16; off > 0; off >>= 1)
        m = fmaxf(m, __shfl_xor_sync(0xffffffffu, m, off));
    float e = (l < H_) ? expf(v - m) : 0.f;
    float s = e;
    #pragma unroll
    for (int off = 16; off > 0; off >>= 1)
        s += __shfl_xor_sync(0xffffffffu, s, off);
    if (l < H_)
        out[BNF + (size_t)wid * H_ + l] = e / s;
}

// ---------------- launch ----------------
extern "C" void kernel_launch(void* const* d_in, const int* in_sizes, int n_in,
                              void* d_out, int out_size)
{
    (void)in_sizes; (void)n_in; (void)out_size;
    const float* Q  = (const float*)d_in[0];
    const float* K  = (const float*)d_in[1];
    const float* V  = (const float*)d_in[2];
    const float* Wq = (const float*)d_in[3];
    const float* bq = (const float*)d_in[4];
    const float* Wk = (const float*)d_in[5];
    const float* bk = (const float*)d_in[6];
    const float* Wv = (const float*)d_in[7];
    const float* bv = (const float*)d_in[8];
    float* out = (float*)d_out;

    // Raise dynamic-smem cap once, outside graph capture (correctness run first).
    static int attr_done = 0;
    if (!attr_done) {
        cudaFuncSetAttribute(k_qwq,     cudaFuncAttributeMaxDynamicSharedMemorySize, SMEM_SZ);
        cudaFuncSetAttribute(k_klogits, cudaFuncAttributeMaxDynamicSharedMemorySize, SMEM_SZ);
        cudaFuncSetAttribute(k_vheads,  cudaFuncAttributeMaxDynamicSharedMemorySize, SMEM_SZ);
        attr_done = 1;
    }

    k_zero<<<(B_ * N_ * F_) / 1024, 256>>>(out);                 // zero heads region
    k_qwq<<<N_, 256, SMEM_SZ>>>(Q, Wq, bq);
    k_klogits<<<dim3(H_ / 3, N_), 256, SMEM_SZ>>>(K, Wk, bk);
    k_softmax<<<(B_ * N_) / 8, 256>>>(out);
    k_vheads<<<dim3(H_ / 3, N_), 256, SMEM_SZ>>>(V, Wv, bv, out);
}

// round 16
// speedup vs baseline: 1.2056x; 1.0608x over previous
#include <cuda_runtime.h>
#include <cuda_bf16.h>
#include <cuda_fp16.h>
#include <cstdint>

#define B_ 64
#define N_ 32
#define H_ 24
#define F_ 256
#define BNF ((size_t)B_ * N_ * F_)

// ---------------- scratch ----------------
__device__ float g_QWq[(size_t)B_ * N_ * F_];              // [b][n][g]
__device__ float g_logits[(size_t)B_ * N_ * H_];           // [b][n][h]

// ---------------- helpers ----------------
__device__ __forceinline__ uint32_t s2u(const void* p) {
    return (uint32_t)__cvta_generic_to_shared(p);
}
__device__ __forceinline__ void cpasync16(uint32_t dst, const void* src) {
    asm volatile("cp.async.cg.shared.global [%0], [%1], 16;" :: "r"(dst), "l"(src));
}
__device__ __forceinline__ void cpcommit() { asm volatile("cp.async.commit_group;"); }
__device__ __forceinline__ void cpwait1() { asm volatile("cp.async.wait_group 1;" ::: "memory"); }
__device__ __forceinline__ void cpwait0() { asm volatile("cp.async.wait_all;" ::: "memory"); }

// bf16 split-pack (3-term path)
__device__ __forceinline__ uint32_t bpack(float a, float b, float& ra, float& rb) {
    __nv_bfloat16 ha = __float2bfloat16(a), hb = __float2bfloat16(b);
    ra = a - __bfloat162float(ha);
    rb = b - __bfloat162float(hb);
    return (uint32_t)__bfloat16_as_ushort(ha) | ((uint32_t)__bfloat16_as_ushort(hb) << 16);
}
__device__ __forceinline__ uint32_t bpack1(float a, float b) {
    __nv_bfloat16 ha = __float2bfloat16(a), hb = __float2bfloat16(b);
    return (uint32_t)__bfloat16_as_ushort(ha) | ((uint32_t)__bfloat16_as_ushort(hb) << 16);
}
// fp16 split-pack (2-term path)
__device__ __forceinline__ uint32_t hpack(float a, float b, float& ra, float& rb) {
    __half ha = __float2half_rn(a), hb = __float2half_rn(b);
    ra = a - __half2float(ha);
    rb = b - __half2float(hb);
    return (uint32_t)__half_as_ushort(ha) | ((uint32_t)__half_as_ushort(hb) << 16);
}
__device__ __forceinline__ uint32_t hpack1(float a, float b) {
    __half ha = __float2half_rn(a), hb = __float2half_rn(b);
    return (uint32_t)__half_as_ushort(ha) | ((uint32_t)__half_as_ushort(hb) << 16);
}
__device__ __forceinline__ uint2 lds64(uint32_t a) {
    uint2 r;
    asm volatile("ld.shared.v2.u32 {%0,%1}, [%2];" : "=r"(r.x), "=r"(r.y) : "r"(a));
    return r;
}
__device__ __forceinline__ void mma4(float* c, uint2 rA, uint2 rA8, uint2 b) {
    asm volatile("mma.sync.aligned.m16n8k16.row.col.f32.bf16.bf16.f32 "
                 "{%0,%1,%2,%3}, {%4,%5,%6,%7}, {%8,%9}, {%0,%1,%2,%3};"
                 : "+f"(c[0]), "+f"(c[1]), "+f"(c[2]), "+f"(c[3])
                 : "r"(rA.x), "r"(rA8.x), "r"(rA.y), "r"(rA8.y), "r"(b.x), "r"(b.y));
}
__device__ __forceinline__ void mma4h(float* c, uint2 rA, uint2 rA8, uint2 b) {
    asm volatile("mma.sync.aligned.m16n8k16.row.col.f32.f16.f16.f32 "
                 "{%0,%1,%2,%3}, {%4,%5,%6,%7}, {%8,%9}, {%0,%1,%2,%3};"
                 : "+f"(c[0]), "+f"(c[1]), "+f"(c[2]), "+f"(c[3])
                 : "r"(rA.x), "r"(rA8.x), "r"(rA.y), "r"(rA8.y), "r"(b.x), "r"(b.y));
}

// smem: raw double-buffered AND converted double-buffered (pipelined)
#define OFF_WRAW 0        // 2 x 16384 fp32 W chunk
#define OFF_ARAW 32768    // 2 x 4096  fp32 A chunk
#define OFF_CB   40960    // 2 x 20480 converted: WH@0, WL@8192, AH@16384, AL@18432
#define CBSZ     20480
#define SMEM_SZ  81920

// MODE: 0 = plain write (+bias), 1 = per-h logits (bf16 3-term),
//       2 = score-scaled A + atomic reduce (fp16 2-term)
template <int HG, int MODE>
__device__ __forceinline__ void proj_run(
    char* smk, uint32_t sb,
    const float* __restrict__ Ab, long aRow, size_t aH,
    const float* __restrict__ Wb, size_t wH,
    const float* __restrict__ biasb, size_t biasH,
    float* __restrict__ outp, long pitch,
    int n, int hg,
    float (*sred)[64], float* sextra, float* sbv)
{
    const int t = threadIdx.x;
    const int w = t >> 5, l = t & 31;
    const int mhalf = w >> 2, wq = w & 3;
    const int c = l & 3;
    const int rho = l >> 2;
    const uint32_t x = ((l >> 4) & 1) << 2;
    const uint32_t woff = (uint32_t)(((2 * c) ^ x) << 2);
    const int NC = 16 * HG;

    float acc[2][8][4];
    #pragma unroll
    for (int i = 0; i < 2; i++)
        #pragma unroll
        for (int j = 0; j < 8; j++)
            #pragma unroll
            for (int k = 0; k < 4; k++) acc[i][j][k] = 0.f;

    const int ar = t >> 2, aq = t & 3;

    auto prefetch = [&](int gc) {
        const int hx = gc >> 4, cc = gc & 15, buf = gc & 1;
        const float* Wp = Wb + (size_t)hx * wH + (size_t)cc * 16 * F_;
        uint32_t wd = sb + OFF_WRAW + buf * 16384;
        #pragma unroll
        for (int q = 0; q < 4; ++q)
            cpasync16(wd + q * 4096 + t * 16, Wp + q * 1024 + t * 4);
        cpasync16(sb + OFF_ARAW + buf * 4096 + t * 16,
                  Ab + (size_t)hx * aH + (long)ar * aRow + cc * 16 + aq * 4);
        cpcommit();
    };

    // convert raw chunk ch -> cbuf[ch&1]
    auto convert = [&](int ch) {
        const int buf = ch & 1;
        char* cbp = smk + OFF_CB + buf * CBSZ;
        {
            const float* wr = (const float*)(smk + OFF_WRAW + buf * 16384);
            float v[16];
            #pragma unroll
            for (int f = 0; f < 16; ++f) v[f] = wr[f * 256 + t];
            uint32_t hi[8], lo[8];
            #pragma unroll
            for (int j = 0; j < 8; ++j) {
                float ra, rb;
                if (MODE == 2) {
                    hi[j] = hpack(v[2 * j], v[2 * j + 1], ra, rb);
                    lo[j] = hpack1(ra, rb);
                } else {
                    hi[j] = bpack(v[2 * j], v[2 * j + 1], ra, rb);
                    lo[j] = bpack1(ra, rb);
                }
            }
            const int s0 = ((t >> 2) & 1) << 4;
            char* bh = cbp + t * 32;
            char* bl = cbp + 8192 + t * 32;
            *(uint4*)(bh + s0)        = make_uint4(hi[0], hi[4], hi[1], hi[5]);
            *(uint4*)(bh + (16 ^ s0)) = make_uint4(hi[2], hi[6], hi[3], hi[7]);
            *(uint4*)(bl + s0)        = make_uint4(lo[0], lo[4], lo[1], lo[5]);
            *(uint4*)(bl + (16 ^ s0)) = make_uint4(lo[2], lo[6], lo[3], lo[7]);
        }
        {
            float4 v = *(const float4*)(smk + OFF_ARAW + buf * 4096 + t * 16);
            const int iw0 = (aq < 2) ? 4 * aq : 4 * aq - 7;
            const int iw1 = (aq < 2) ? 4 * aq + 2 : 4 * aq - 5;
            const int x4 = ((ar >> 2) & 1) << 2;
            char* ah = cbp + 16384 + ar * 32;
            if (MODE == 2) {
                // fp16 hi only (2-term: dropped al*b term is ~2^-11 relative)
                const float sc = sextra[(ch >> 4) * 64 + ar];
                v.x *= sc; v.y *= sc; v.z *= sc; v.w *= sc;
                float r0, r1, r2, r3;
                uint32_t h0 = hpack(v.x, v.y, r0, r1);
                uint32_t h1 = hpack(v.z, v.w, r2, r3);
                *(uint32_t*)(ah + ((iw0 ^ x4) << 2)) = h0;
                *(uint32_t*)(ah + ((iw1 ^ x4) << 2)) = h1;
            } else {
                float r0, r1, r2, r3;
                uint32_t h0 = bpack(v.x, v.y, r0, r1);
                uint32_t h1 = bpack(v.z, v.w, r2, r3);
                uint32_t l0 = bpack1(r0, r1);
                uint32_t l1 = bpack1(r2, r3);
                char* al = cbp + 18432 + ar * 32;
                *(uint32_t*)(ah + ((iw0 ^ x4) << 2)) = h0;
                *(uint32_t*)(ah + ((iw1 ^ x4) << 2)) = h1;
                *(uint32_t*)(al + ((iw0 ^ x4) << 2)) = l0;
                *(uint32_t*)(al + ((iw1 ^ x4) << 2)) = l1;
            }
        }
    };

    prefetch(0);
    prefetch(1);

    // MODE2: stage scores (sextra[HG][64]) and bias rows (sbv[HG][256])
    if (MODE == 2) {
        if (t < HG * 64) {
            const int i = t >> 6, b = t & 63;
            sextra[i * 64 + b] = outp[BNF + ((size_t)b * N_ + n) * H_ + hg * HG + i];
        }
        #pragma unroll
        for (int i = 0; i < HG; ++i)
            sbv[i * 256 + t] = biasb[(size_t)i * biasH + t];
    }

    cpwait1();
    __syncthreads();      // publish raw0 + MODE2 staging
    convert(0);

    #pragma unroll 1
    for (int gc = 0; gc < NC; ++gc) {
        if (gc + 2 < NC) prefetch(gc + 2);
        if (gc + 1 < NC) { if (gc + 2 < NC) cpwait1(); else cpwait0(); }
        __syncthreads();  // publish cbuf[gc&1] + raw gc+1

        if (gc + 1 < NC) convert(gc + 1);   // overlaps this chunk's MMAs

        const uint32_t cb = sb + OFF_CB + (uint32_t)(gc & 1) * CBSZ;
        if (MODE == 2) {
            // fp16 2-term: ah*(bh+bl)
            uint2 fa[2][2];
            #pragma unroll
            for (int mt = 0; mt < 2; ++mt) {
                const int r1 = mhalf * 32 + mt * 16 + rho;
                fa[mt][0] = lds64(cb + 16384 + r1 * 32 + woff);
                fa[mt][1] = lds64(cb + 16384 + (r1 + 8) * 32 + woff);
            }
            #pragma unroll
            for (int nt = 0; nt < 8; ++nt) {
                const int g = wq * 64 + nt * 8 + rho;
                uint2 bh = lds64(cb + g * 32 + woff);
                uint2 bl = lds64(cb + 8192 + g * 32 + woff);
                #pragma unroll
                for (int mt = 0; mt < 2; ++mt) {
                    mma4h(acc[mt][nt], fa[mt][0], fa[mt][1], bh);
                    mma4h(acc[mt][nt], fa[mt][0], fa[mt][1], bl);
                }
            }
        } else {
            // bf16 3-term
            uint2 fa[2][4];
            #pragma unroll
            for (int mt = 0; mt < 2; ++mt) {
                const int r1 = mhalf * 32 + mt * 16 + rho;
                fa[mt][0] = lds64(cb + 16384 + r1 * 32 + woff);
                fa[mt][1] = lds64(cb + 16384 + (r1 + 8) * 32 + woff);
                fa[mt][2] = lds64(cb + 18432 + r1 * 32 + woff);
                fa[mt][3] = lds64(cb + 18432 + (r1 + 8) * 32 + woff);
            }
            #pragma unroll
            for (int nt = 0; nt < 8; ++nt) {
                const int g = wq * 64 + nt * 8 + rho;
                uint2 bh = lds64(cb + g * 32 + woff);
                uint2 bl = lds64(cb + 8192 + g * 32 + woff);
                #pragma unroll
                for (int mt = 0; mt < 2; ++mt) {
                    mma4(acc[mt][nt], fa[mt][0], fa[mt][1], bh);
                    mma4(acc[mt][nt], fa[mt][0], fa[mt][1], bl);
                    mma4(acc[mt][nt], fa[mt][2], fa[mt][3], bh);
                }
            }
        }

        // ---- epilogues ----
        if (MODE == 1 && (gc & 15) == 15) {
            const int hx = gc >> 4;
            const int h = hg * HG + hx;
            const float* bkp = biasb + (size_t)hx * biasH;
            float p[4] = {0.f, 0.f, 0.f, 0.f};
            #pragma unroll
            for (int nt = 0; nt < 8; ++nt) {
                const int g0 = wq * 64 + nt * 8 + 2 * c;
                const float2 bkv = *(const float2*)(bkp + g0);
                #pragma unroll
                for (int rr = 0; rr < 4; ++rr) {
                    const int row = mhalf * 32 + (rr >> 1) * 16 + (rr & 1) * 8 + rho;
                    const float2 qv = *(const float2*)(g_QWq + ((size_t)row * N_ + n) * F_ + g0);
                    p[rr] += (acc[rr >> 1][nt][(rr & 1) * 2]     + bkv.x) * qv.x
                           + (acc[rr >> 1][nt][(rr & 1) * 2 + 1] + bkv.y) * qv.y;
                }
            }
            #pragma unroll
            for (int rr = 0; rr < 4; ++rr) {
                p[rr] += __shfl_xor_sync(0xffffffffu, p[rr], 1);
                p[rr] += __shfl_xor_sync(0xffffffffu, p[rr], 2);
            }
            if (c == 0) {
                #pragma unroll
                for (int rr = 0; rr < 4; ++rr)
                    sred[wq][mhalf * 32 + (rr >> 1) * 16 + (rr & 1) * 8 + rho] = p[rr];
            }
            __syncthreads();
            if (t < 64)
                g_logits[((size_t)t * N_ + n) * H_ + h]
                    = sred[0][t] + sred[1][t] + sred[2][t] + sred[3][t];
            #pragma unroll
            for (int i = 0; i < 2; i++)
                #pragma unroll
                for (int j = 0; j < 8; j++)
                    #pragma unroll
                    for (int k = 0; k < 4; k++) acc[i][j][k] = 0.f;
        }
        if (MODE == 0 && gc == NC - 1) {
            #pragma unroll
            for (int nt = 0; nt < 8; ++nt) {
                const int g0 = wq * 64 + nt * 8 + 2 * c;
                const float2 bv2 = *(const float2*)(biasb + g0);
                #pragma unroll
                for (int mt = 0; mt < 2; ++mt) {
                    const int r1 = mhalf * 32 + mt * 16 + rho;
                    float2 v0, v1;
                    v0.x = acc[mt][nt][0] + bv2.x; v0.y = acc[mt][nt][1] + bv2.y;
                    v1.x = acc[mt][nt][2] + bv2.x; v1.y = acc[mt][nt][3] + bv2.y;
                    *(float2*)(outp + (long)r1 * pitch + g0) = v0;
                    *(float2*)(outp + (long)(r1 + 8) * pitch + g0) = v1;
                }
            }
        }
        if (MODE == 2 && gc == NC - 1) {
            float sA[2][HG], sB[2][HG];
            #pragma unroll
            for (int mt = 0; mt < 2; ++mt) {
                const int r1 = mhalf * 32 + mt * 16 + rho;
                #pragma unroll
                for (int i = 0; i < HG; ++i) {
                    sA[mt][i] = sextra[i * 64 + r1];
                    sB[mt][i] = sextra[i * 64 + r1 + 8];
                }
            }
            #pragma unroll
            for (int nt = 0; nt < 8; ++nt) {
                const int g0 = wq * 64 + nt * 8 + 2 * c;
                float bx[HG], by[HG];
                #pragma unroll
                for (int i = 0; i < HG; ++i) {
                    bx[i] = sbv[i * 256 + g0];
                    by[i] = sbv[i * 256 + g0 + 1];
                }
                #pragma unroll
                for (int mt = 0; mt < 2; ++mt) {
                    const int r1 = mhalf * 32 + mt * 16 + rho;
                    float vx = acc[mt][nt][0], vy = acc[mt][nt][1];
                    float wx = acc[mt][nt][2], wy = acc[mt][nt][3];
                    #pragma unroll
                    for (int i = 0; i < HG; ++i) {
                        vx += sA[mt][i] * bx[i]; vy += sA[mt][i] * by[i];
                        wx += sB[mt][i] * bx[i]; wy += sB[mt][i] * by[i];
                    }
                    float* o0 = outp + ((size_t)r1 * N_ + n) * F_ + g0;
                    float* o1 = outp + ((size_t)(r1 + 8) * N_ + n) * F_ + g0;
                    atomicAdd(o0, vx);     atomicAdd(o0 + 1, vy);
                    atomicAdd(o1, wx);     atomicAdd(o1 + 1, wy);
                }
            }
        }
        __syncthreads();   // cbuf/raw reuse guard
    }
}

// ---------------- kernels ----------------
__global__ void __launch_bounds__(256, 2) k_qwq(const float* __restrict__ Q,
                                                const float* __restrict__ Wq,
                                                const float* __restrict__ bq)
{
    extern __shared__ char smk[];
    const int n = blockIdx.x;
    proj_run<1, 0>(smk, s2u(smk),
                   Q + (size_t)n * F_, (long)N_ * F_, 0,
                   Wq + (size_t)n * F_ * F_, 0,
                   bq + (size_t)n * F_, 0,
                   g_QWq + (size_t)n * F_, (long)N_ * F_,
                   n, 0, nullptr, nullptr, nullptr);
}

__global__ void __launch_bounds__(256, 2) k_klogits(const float* __restrict__ Kt,
                                                    const float* __restrict__ Wk,
                                                    const float* __restrict__ bk)
{
    extern __shared__ char smk[];
    __shared__ float sred[4][64];
    const int hg = blockIdx.x, n = blockIdx.y;
    const size_t nh0 = (size_t)n * H_ + hg * 3;
    proj_run<3, 1>(smk, s2u(smk),
                   Kt + ((size_t)(hg * 3) * N_ + n) * F_, (long)H_ * N_ * F_, (size_t)N_ * F_,
                   Wk + nh0 * F_ * F_, (size_t)F_ * F_,
                   bk + nh0 * F_, F_,
                   nullptr, 0, n, hg, sred, nullptr, nullptr);
}

__global__ void __launch_bounds__(256, 2) k_vheads(const float* __restrict__ Vt,
                                                   const float* __restrict__ Wv,
                                                   const float* __restrict__ bv,
                                                   float* __restrict__ out)
{
    extern __shared__ char smk[];
    __shared__ float sextra[3 * 64];
    __shared__ float sbv[3 * 256];
    const int hg = blockIdx.x, n = blockIdx.y;
    const size_t nh0 = (size_t)n * H_ + hg * 3;
    proj_run<3, 2>(smk, s2u(smk),
                   Vt + ((size_t)(hg * 3) * N_ + n) * F_, (long)H_ * N_ * F_, (size_t)N_ * F_,
                   Wv + nh0 * F_ * F_, (size_t)F_ * F_,
                   bv + nh0 * F_, F_,
                   out, 0, n, hg, nullptr, sextra, sbv);
}

__global__ void k_zero(float* __restrict__ out)
{
    const size_t i = (size_t)blockIdx.x * 256 + threadIdx.x;
    *(float4*)(out + i * 4) = make_float4(0.f, 0.f, 0.f, 0.f);
}

// softmax: one warp per (b,n) row
__global__ void __launch_bounds__(256) k_softmax(float* __restrict__ out)
{
    const int wid = (blockIdx.x * 256 + threadIdx.x) >> 5;   // b*N+n
    const int l = threadIdx.x & 31;
    float v = (l < H_) ? g_logits[(size_t)wid * H_ + l] : -3.4e38f;
    float m = v;
    #pragma unroll
    for (int off = 16; off > 0; off >>= 1)
        m = fmaxf(m, __shfl_xor_sync(0xffffffffu, m, off));
    float e = (l < H_) ? expf(v - m) : 0.f;
    float s = e;
    #pragma unroll
    for (int off = 16; off > 0; off >>= 1)
        s += __shfl_xor_sync(0xffffffffu, s, off);
    if (l < H_)
        out[BNF + (size_t)wid * H_ + l] = e / s;
}

// ---------------- launch ----------------
extern "C" void kernel_launch(void* const* d_in, const int* in_sizes, int n_in,
                              void* d_out, int out_size)
{
    (void)in_sizes; (void)n_in; (void)out_size;
    const float* Q  = (const float*)d_in[0];
    const float* K  = (const float*)d_in[1];
    const float* V  = (const float*)d_in[2];
    const float* Wq = (const float*)d_in[3];
    const float* bq = (const float*)d_in[4];
    const float* Wk = (const float*)d_in[5];
    const float* bk = (const float*)d_in[6];
    const float* Wv = (const float*)d_in[7];
    const float* bv = (const float*)d_in[8];
    float* out = (float*)d_out;

    // Raise dynamic-smem cap once, outside graph capture (correctness run first).
    static int attr_done = 0;
    if (!attr_done) {
        cudaFuncSetAttribute(k_qwq,     cudaFuncAttributeMaxDynamicSharedMemorySize, SMEM_SZ);
        cudaFuncSetAttribute(k_klogits, cudaFuncAttributeMaxDynamicSharedMemorySize, SMEM_SZ);
        cudaFuncSetAttribute(k_vheads,  cudaFuncAttributeMaxDynamicSharedMemorySize, SMEM_SZ);
        attr_done = 1;
    }

    k_zero<<<(B_ * N_ * F_) / 1024, 256>>>(out);
    k_qwq<<<N_, 256, SMEM_SZ>>>(Q, Wq, bq);
    k_klogits<<<dim3(H_ / 3, N_), 256, SMEM_SZ>>>(K, Wk, bk);
    k_softmax<<<(B_ * N_) / 8, 256>>>(out);
    k_vheads<<<dim3(H_ / 3, N_), 256, SMEM_SZ>>>(V, Wv, bv, out);
}